// round 1
// baseline (speedup 1.0000x reference)
#include <cuda_runtime.h>
#include <cstdint>

// ---------------------------------------------------------------------------
// Scratch (static __device__ globals; no allocation allowed)
// ---------------------------------------------------------------------------
__device__ float g_bufA[33554432];   // 134 MB ping
__device__ float g_bufB[33554432];   // 134 MB pong
__device__ float g_bufP[4194304];    // 16.8 MB split-K partials
__device__ float g_mean[1024];
__device__ float g_rstd[1024];

__device__ __forceinline__ float lrelu(float v) { return v >= 0.f ? v : 0.01f * v; }

// ---------------------------------------------------------------------------
// Generic fused 3x3 conv kernel.
// MODE 0: conv(SAME) fused with stride-2 subsample (encoder)
// MODE 1: plain conv(SAME) stride 1 (inner)
// MODE 2: zero-insert upsample fused with conv(SAME) (decoder, sparse taps)
// Each thread computes COT output channels x PX horizontally-adjacent pixels.
// SPLIT>1: blockIdx.x indexes a Ci-split; raw partial sums are written to
//          out + split*N*Co*H*W (bias/activation applied in reduce kernel).
// ---------------------------------------------------------------------------
template <int MODE, int TX, int TY, int PX, int COT, int CHUNK, int SPLIT>
__global__ void __launch_bounds__(TX * TY) conv3_kernel(
    const float* __restrict__ in, const float* __restrict__ wt,
    const float* __restrict__ bias, float* __restrict__ out,
    int N, int Ci, int Co, int Hout, int Wout, int act)
{
    constexpr int NT = TX * TY;
    constexpr int TW = TX * PX;                 // tile width (outputs)
    constexpr int SH = (MODE == 0) ? (2 * TY + 1) : (MODE == 2 ? (TY / 2 + 1) : (TY + 2));
    constexpr int SW = (MODE == 0) ? (2 * TW + 1) : (MODE == 2 ? (TW / 2 + 1) : (TW + 2));

    __shared__ float s_in[CHUNK][SH][SW];
    __shared__ float s_w[CHUNK][COT][9];

    const int Hin = (MODE == 0) ? Hout * 2 : (MODE == 2 ? Hout / 2 : Hout);
    const int Win = (MODE == 0) ? Wout * 2 : (MODE == 2 ? Wout / 2 : Wout);

    const int gpc = Co / COT;
    const int n   = blockIdx.z / gpc;
    const int co0 = (blockIdx.z % gpc) * COT;
    const int oh0 = blockIdx.y * TY;
    const int bxs = (SPLIT == 1) ? blockIdx.x : 0;
    const int ow0 = bxs * TW;

    const int tid = threadIdx.x;
    const int tx  = tid % TX;
    const int ty  = tid / TX;
    const int oh  = oh0 + ty;
    const int owb = ow0 + tx * PX;

    const int iy0 = (MODE == 0) ? (2 * oh0 - 1) : (MODE == 2 ? (oh0 >> 1) : (oh0 - 1));
    const int ix0 = (MODE == 0) ? (2 * ow0 - 1) : (MODE == 2 ? (ow0 >> 1) : (ow0 - 1));

    float acc[COT][PX];
#pragma unroll
    for (int c = 0; c < COT; c++)
#pragma unroll
        for (int p = 0; p < PX; p++) acc[c][p] = 0.f;

    const float* inN = in + (size_t)n * Ci * Hin * Win;

    int ciB = 0, ciE = Ci;
    if (SPLIT > 1) { ciB = blockIdx.x * (Ci / SPLIT); ciE = ciB + Ci / SPLIT; }

    for (int ci0 = ciB; ci0 < ciE; ci0 += CHUNK) {
        __syncthreads();
        // weights for this ci-chunk
        for (int j = tid; j < CHUNK * COT * 9; j += NT) {
            int cc = j / (COT * 9);
            int r  = j % (COT * 9);
            int co = r / 9;
            int k  = r % 9;
            s_w[cc][co][k] = wt[((size_t)(co0 + co) * Ci + (ci0 + cc)) * 9 + k];
        }
        // input patch for this ci-chunk (zero-padded at borders)
        for (int j = tid; j < CHUNK * SH * SW; j += NT) {
            int cc = j / (SH * SW);
            int r2 = j % (SH * SW);
            int r  = r2 / SW;
            int c  = r2 % SW;
            int iy = iy0 + r, ix = ix0 + c;
            float v = 0.f;
            if ((unsigned)iy < (unsigned)Hin && (unsigned)ix < (unsigned)Win)
                v = inN[(size_t)(ci0 + cc) * Hin * Win + (size_t)iy * Win + ix];
            (&s_in[0][0][0])[j] = v;
        }
        __syncthreads();

#pragma unroll
        for (int cc = 0; cc < CHUNK; cc++) {
            if (MODE == 1) {
                float rin[3][PX + 2];
#pragma unroll
                for (int kh = 0; kh < 3; kh++)
#pragma unroll
                    for (int c = 0; c < PX + 2; c++)
                        rin[kh][c] = s_in[cc][ty + kh][tx * PX + c];
#pragma unroll
                for (int co = 0; co < COT; co++)
#pragma unroll
                    for (int kh = 0; kh < 3; kh++)
#pragma unroll
                        for (int kw = 0; kw < 3; kw++) {
                            float w = s_w[cc][co][kh * 3 + kw];
#pragma unroll
                            for (int p = 0; p < PX; p++)
                                acc[co][p] += rin[kh][p + kw] * w;
                        }
            } else if (MODE == 0) {
                float rin[3][2 * PX + 1];
#pragma unroll
                for (int kh = 0; kh < 3; kh++)
#pragma unroll
                    for (int q = 0; q < 2 * PX + 1; q++)
                        rin[kh][q] = s_in[cc][2 * ty + kh][2 * tx * PX + q];
#pragma unroll
                for (int co = 0; co < COT; co++)
#pragma unroll
                    for (int kh = 0; kh < 3; kh++)
#pragma unroll
                        for (int kw = 0; kw < 3; kw++) {
                            float w = s_w[cc][co][kh * 3 + kw];
#pragma unroll
                            for (int p = 0; p < PX; p++)
                                acc[co][p] += rin[kh][2 * p + kw] * w;
                        }
            } else {  // MODE 2: zero-insert upsample + conv (sparse taps)
                const int r0 = ty >> 1;
                const int cb = (tx * PX) >> 1;
                float rin[2][PX / 2 + 1];
#pragma unroll
                for (int i = 0; i < 2; i++)
#pragma unroll
                    for (int c = 0; c < PX / 2 + 1; c++)
                        rin[i][c] = s_in[cc][r0 + i][cb + c];
                const bool oddr = (ty & 1);
#pragma unroll
                for (int co = 0; co < COT; co++) {
                    const float* wp = &s_w[cc][co][0];
                    if (!oddr) {
                        float w10 = wp[3], w11 = wp[4], w12 = wp[5];
#pragma unroll
                        for (int p = 0; p < PX; p++) {
                            if ((p & 1) == 0) {
                                acc[co][p] += rin[0][p >> 1] * w11;
                            } else {
                                acc[co][p] += rin[0][p >> 1] * w10 + rin[0][(p >> 1) + 1] * w12;
                            }
                        }
                    } else {
                        float w00 = wp[0], w01 = wp[1], w02 = wp[2];
                        float w20 = wp[6], w21 = wp[7], w22 = wp[8];
#pragma unroll
                        for (int p = 0; p < PX; p++) {
                            if ((p & 1) == 0) {
                                acc[co][p] += rin[0][p >> 1] * w01 + rin[1][p >> 1] * w21;
                            } else {
                                int cl = p >> 1, cr = cl + 1;
                                acc[co][p] += rin[0][cl] * w00 + rin[0][cr] * w02
                                            + rin[1][cl] * w20 + rin[1][cr] * w22;
                            }
                        }
                    }
                }
            }
        }
    }

    if (SPLIT == 1) {
#pragma unroll
        for (int co = 0; co < COT; co++) {
            float b = __ldg(&bias[co0 + co]);
#pragma unroll
            for (int p = 0; p < PX; p++) {
                float v = acc[co][p] + b;
                if (act) v = lrelu(v);
                out[((size_t)(n * Co + co0 + co) * Hout + oh) * Wout + owb + p] = v;
            }
        }
    } else {
        float* po = out + (size_t)blockIdx.x * ((size_t)N * Co * Hout * Wout);
#pragma unroll
        for (int co = 0; co < COT; co++)
#pragma unroll
            for (int p = 0; p < PX; p++)
                po[((size_t)(n * Co + co0 + co) * Hout + oh) * Wout + owb + p] = acc[co][p];
    }
}

// ---------------------------------------------------------------------------
// split-K reduce: sum S partials, add bias, optional LReLU
// ---------------------------------------------------------------------------
__global__ void splitk_reduce_kernel(const float* __restrict__ part,
                                     const float* __restrict__ bias,
                                     float* __restrict__ out,
                                     int S, int per, int HW, int Co, int act)
{
    int i = blockIdx.x * blockDim.x + threadIdx.x;
    if (i >= per) return;
    float s = 0.f;
    for (int k = 0; k < S; k++) s += part[(size_t)k * per + i];
    int c = (i / HW) % Co;
    float v = s + __ldg(&bias[c]);
    if (act) v = lrelu(v);
    out[i] = v;
}

// ---------------------------------------------------------------------------
// BatchNorm: per-channel batch stats over (N, H, W); N*HW = 512 elements.
// ---------------------------------------------------------------------------
__global__ void bn_stats_kernel(const float* __restrict__ x, int N, int C, int HW)
{
    int c = blockIdx.x;
    int tot = N * HW;
    float s = 0.f, s2 = 0.f;
    for (int i = threadIdx.x; i < tot; i += blockDim.x) {
        int nn = i / HW, r = i % HW;
        float v = x[((size_t)nn * C + c) * HW + r];
        s += v;
        s2 += v * v;
    }
    __shared__ float rs[256], rq[256];
    rs[threadIdx.x] = s;
    rq[threadIdx.x] = s2;
    __syncthreads();
    for (int off = 128; off > 0; off >>= 1) {
        if (threadIdx.x < off) {
            rs[threadIdx.x] += rs[threadIdx.x + off];
            rq[threadIdx.x] += rq[threadIdx.x + off];
        }
        __syncthreads();
    }
    if (threadIdx.x == 0) {
        float m   = rs[0] / tot;
        float var = rq[0] / tot - m * m;
        g_mean[c] = m;
        g_rstd[c] = rsqrtf(var + 1e-5f);
    }
}

__global__ void bn_apply_kernel(float* __restrict__ x,
                                const float* __restrict__ gamma,
                                const float* __restrict__ beta,
                                int C, int HW, int total)
{
    int i = blockIdx.x * blockDim.x + threadIdx.x;
    if (i >= total) return;
    int c = (i / HW) % C;
    float v = (x[i] - g_mean[c]) * g_rstd[c] * __ldg(&gamma[c]) + __ldg(&beta[c]);
    x[i] = lrelu(v);
}

// ---------------------------------------------------------------------------
// Epilogue: 1x1 conv 64 -> 3
// ---------------------------------------------------------------------------
__global__ void ep_kernel(const float* __restrict__ in, const float* __restrict__ w,
                          const float* __restrict__ b, float* __restrict__ out,
                          int HW, int total)
{
    int i = blockIdx.x * blockDim.x + threadIdx.x;
    if (i >= total) return;
    int n = i / HW;
    int r = i - n * HW;
    const float* ip = in + (size_t)n * 64 * HW + r;
    float a0 = __ldg(&b[0]), a1 = __ldg(&b[1]), a2 = __ldg(&b[2]);
#pragma unroll
    for (int c = 0; c < 64; c++) {
        float v = ip[(size_t)c * HW];
        a0 += v * __ldg(&w[c]);
        a1 += v * __ldg(&w[64 + c]);
        a2 += v * __ldg(&w[128 + c]);
    }
    out[((size_t)n * 3 + 0) * HW + r] = a0;
    out[((size_t)n * 3 + 1) * HW + r] = a1;
    out[((size_t)n * 3 + 2) * HW + r] = a2;
}

// ---------------------------------------------------------------------------
// Launch sequence
// ---------------------------------------------------------------------------
extern "C" void kernel_launch(void* const* d_in, const int* in_sizes, int n_in,
                              void* d_out, int out_size)
{
    (void)in_sizes; (void)n_in; (void)out_size;
    const float* x     = (const float*)d_in[0];
    const float* wd0   = (const float*)d_in[1];
    const float* bd0   = (const float*)d_in[2];
    const float* wd1   = (const float*)d_in[3];
    const float* bd1   = (const float*)d_in[4];
    const float* wd2   = (const float*)d_in[5];
    const float* bd2   = (const float*)d_in[6];
    const float* wd3   = (const float*)d_in[7];
    const float* bd3   = (const float*)d_in[8];
    const float* wd4   = (const float*)d_in[9];
    const float* bd4   = (const float*)d_in[10];
    const float* w_in  = (const float*)d_in[11];
    const float* b_in  = (const float*)d_in[12];
    const float* gamma = (const float*)d_in[13];
    const float* beta  = (const float*)d_in[14];
    const float* wu0   = (const float*)d_in[15];
    const float* bu0   = (const float*)d_in[16];
    const float* wu1   = (const float*)d_in[17];
    const float* bu1   = (const float*)d_in[18];
    const float* wu2   = (const float*)d_in[19];
    const float* bu2   = (const float*)d_in[20];
    const float* wu3   = (const float*)d_in[21];
    const float* bu3   = (const float*)d_in[22];
    const float* wu4   = (const float*)d_in[23];
    const float* bu4   = (const float*)d_in[24];
    const float* wep   = (const float*)d_in[25];
    const float* bep   = (const float*)d_in[26];
    float* outp = (float*)d_out;

    float *A, *B, *P;
    cudaGetSymbolAddress((void**)&A, g_bufA);
    cudaGetSymbolAddress((void**)&B, g_bufB);
    cudaGetSymbolAddress((void**)&P, g_bufP);

    // --------------- encoder (fused conv+lrelu+down2 via stride-2) ----------
    // d0: 3->64, out 256x256
    conv3_kernel<0, 16, 4, 4, 8, 1, 1><<<dim3(4, 64, 16), 64>>>(x, wd0, bd0, A, 2, 3, 64, 256, 256, 1);
    // d1: 64->128, out 128x128
    conv3_kernel<0, 16, 4, 4, 8, 4, 1><<<dim3(2, 32, 32), 64>>>(A, wd1, bd1, B, 2, 64, 128, 128, 128, 1);
    // d2: 128->256, out 64x64
    conv3_kernel<0, 16, 4, 4, 8, 4, 1><<<dim3(1, 16, 64), 64>>>(B, wd2, bd2, A, 2, 128, 256, 64, 64, 1);
    // d3: 256->512, out 32x32 (split-K=2)
    conv3_kernel<0, 8, 8, 4, 8, 4, 2><<<dim3(2, 4, 128), 64>>>(A, wd3, bd3, P, 2, 256, 512, 32, 32, 0);
    splitk_reduce_kernel<<<(2 * 512 * 32 * 32 + 255) / 256, 256>>>(P, bd3, B, 2, 2 * 512 * 32 * 32, 1024, 512, 1);
    // d4: 512->1024, out 16x16 (split-K=8)
    conv3_kernel<0, 4, 16, 4, 8, 4, 8><<<dim3(8, 1, 256), 64>>>(B, wd4, bd4, P, 2, 512, 1024, 16, 16, 0);
    splitk_reduce_kernel<<<(2 * 1024 * 16 * 16 + 255) / 256, 256>>>(P, bd4, A, 8, 2 * 1024 * 16 * 16, 256, 1024, 1);

    // --------------- innermost conv + BN + lrelu ---------------------------
    conv3_kernel<1, 4, 16, 4, 8, 4, 8><<<dim3(8, 1, 256), 64>>>(A, w_in, b_in, P, 2, 1024, 1024, 16, 16, 0);
    splitk_reduce_kernel<<<(2 * 1024 * 16 * 16 + 255) / 256, 256>>>(P, b_in, B, 8, 2 * 1024 * 16 * 16, 256, 1024, 0);
    bn_stats_kernel<<<1024, 256>>>(B, 2, 1024, 256);
    bn_apply_kernel<<<(2 * 1024 * 256 + 255) / 256, 256>>>(B, gamma, beta, 1024, 256, 2 * 1024 * 256);

    // --------------- decoder (fused up2+conv+lrelu, sparse taps) -----------
    // u0: 1024->512, out 32x32 (split-K=4)
    conv3_kernel<2, 8, 8, 4, 8, 4, 4><<<dim3(4, 4, 128), 64>>>(B, wu0, bu0, P, 2, 1024, 512, 32, 32, 0);
    splitk_reduce_kernel<<<(2 * 512 * 32 * 32 + 255) / 256, 256>>>(P, bu0, A, 4, 2 * 512 * 32 * 32, 1024, 512, 1);
    // u1: 512->256, out 64x64
    conv3_kernel<2, 16, 4, 4, 8, 4, 1><<<dim3(1, 16, 64), 64>>>(A, wu1, bu1, B, 2, 512, 256, 64, 64, 1);
    // u2: 256->128, out 128x128
    conv3_kernel<2, 16, 4, 4, 8, 4, 1><<<dim3(2, 32, 32), 64>>>(B, wu2, bu2, A, 2, 256, 128, 128, 128, 1);
    // u3: 128->64, out 256x256
    conv3_kernel<2, 16, 4, 4, 8, 4, 1><<<dim3(4, 64, 16), 64>>>(A, wu3, bu3, B, 2, 128, 64, 256, 256, 1);
    // u4: 64->64, out 512x512
    conv3_kernel<2, 16, 4, 4, 8, 4, 1><<<dim3(8, 128, 16), 64>>>(B, wu4, bu4, A, 2, 64, 64, 512, 512, 1);

    // --------------- epilogue 1x1 ------------------------------------------
    ep_kernel<<<(2 * 512 * 512 + 255) / 256, 256>>>(A, wep, bep, outp, 512 * 512, 2 * 512 * 512);
}

// round 2
// speedup vs baseline: 1.2245x; 1.2245x over previous
#include <cuda_runtime.h>
#include <cstdint>

// ---------------------------------------------------------------------------
// Scratch (static __device__ globals; no allocation allowed)
// ---------------------------------------------------------------------------
__device__ float g_bufA[33554432];   // ping
__device__ float g_bufB[33554432];   // pong
__device__ float g_bufP[16777216];   // split-K partials
__device__ float g_mean[1024];
__device__ float g_rstd[1024];

__device__ __forceinline__ float lrelu(float v) { return v >= 0.f ? v : 0.01f * v; }

// ---------------------------------------------------------------------------
// Fused 3x3 conv.
// MODE 0: SAME conv + stride-2 subsample (encoder stage)
// MODE 1: SAME conv stride 1 (inner)
// MODE 2: zero-insert upsample + SAME conv (decoder), "output quad" form:
//         each thread computes 2 output rows x PX output cols (PX/2 quads),
//         exactly 9 taps per quad -> no divergence, no imbalance.
// Thread block: TX*TY*CG threads. CG channel-groups share one smem patch;
// each thread computes COT channels x (PX or 2xPX) outputs.
// SPLIT>1: blockIdx.x = Ci-split index; raw partials to out + split*N*Co*H*W.
// ---------------------------------------------------------------------------
template <int MODE, int TX, int TY, int PX, int COT, int CG, int CHUNK, int SPLIT>
__global__ void __launch_bounds__(TX * TY * CG) conv3(
    const float* __restrict__ in, const float* __restrict__ wt,
    const float* __restrict__ bias, float* __restrict__ out,
    int N, int Ci, int Co, int Hout, int Wout, int act)
{
    constexpr int NT  = TX * TY * CG;
    constexpr int PT  = TX * TY;                    // pixel threads per cg
    constexpr int TW  = TX * PX;                    // output tile width
    constexpr int THO = (MODE == 2) ? 2 * TY : TY;  // output tile height
    constexpr int SH  = (MODE == 0) ? 2 * TY + 1 : (MODE == 1 ? TY + 2 : TY + 1);
    constexpr int SW  = (MODE == 0) ? 2 * TW + 1 : (MODE == 1 ? TW + 2 : TW / 2 + 1);
    constexpr int QX  = PX / 2;
    constexpr int CGC = CG * COT;
    constexpr int NACC = (MODE == 2) ? 2 * PX : PX;

    __shared__ float s_in[CHUNK][SH][SW];
    __shared__ float s_w[CHUNK][CGC][9];

    const int Hin  = (MODE == 0) ? 2 * Hout : (MODE == 2 ? Hout / 2 : Hout);
    const int Win  = (MODE == 0) ? 2 * Wout : (MODE == 2 ? Wout / 2 : Wout);
    const int HWin = Hin * Win;

    const int gpc = Co / CGC;
    const int n   = blockIdx.z / gpc;
    const int cob = (blockIdx.z % gpc) * CGC;

    const int tid = threadIdx.x;
    const int cg  = tid / PT;
    const int pxt = tid % PT;
    const int tx  = pxt % TX;
    const int ty  = pxt / TX;

    const int bx  = (SPLIT == 1) ? blockIdx.x : 0;
    const int ow0 = bx * TW;
    const int oh0 = blockIdx.y * THO;
    const int iy0 = (MODE == 0) ? 2 * oh0 - 1 : (MODE == 1 ? oh0 - 1 : oh0 / 2);
    const int ix0 = (MODE == 0) ? 2 * ow0 - 1 : (MODE == 1 ? ow0 - 1 : ow0 / 2);

    float acc[COT][NACC];
#pragma unroll
    for (int c = 0; c < COT; c++)
#pragma unroll
        for (int p = 0; p < NACC; p++) acc[c][p] = 0.f;

    const float* inN = in + (size_t)n * Ci * HWin;

    int ciB = 0, ciE = Ci;
    if (SPLIT > 1) { int cs = Ci / SPLIT; ciB = blockIdx.x * cs; ciE = ciB + cs; }

    const int rT = tid >> 5;
    const int cT = tid & 31;
    constexpr int NR = NT / 32;

    for (int ci0 = ciB; ci0 < ciE; ci0 += CHUNK) {
        __syncthreads();
        // ---- weights for this ci-chunk ----
#pragma unroll 1
        for (int j = tid; j < CHUNK * CGC * 9; j += NT) {
            int cc = j / (CGC * 9);
            int r  = j - cc * (CGC * 9);
            int co = r / 9;
            int k  = r - co * 9;
            s_w[cc][co][k] = wt[((size_t)(cob + co) * Ci + (ci0 + cc)) * 9 + k];
        }
        // ---- input patch (row/col structured, no div/mod) ----
#pragma unroll 1
        for (int cc = 0; cc < CHUNK; cc++) {
            const float* src = inN + (size_t)(ci0 + cc) * HWin;
#pragma unroll 1
            for (int r = rT; r < SH; r += NR) {
                int iy = iy0 + r;
                bool rok = ((unsigned)iy < (unsigned)Hin);
                const float* srow = src + (size_t)iy * Win;
                for (int c = cT; c < SW; c += 32) {
                    int ix = ix0 + c;
                    float v = 0.f;
                    if (rok && (unsigned)ix < (unsigned)Win) v = srow[ix];
                    s_in[cc][r][c] = v;
                }
            }
        }
        __syncthreads();

        // ---- compute ----
#pragma unroll 2
        for (int cc = 0; cc < CHUNK; cc++) {
            const float(*wp)[9] = s_w[cc] + cg * COT;
            if (MODE == 0) {
#pragma unroll
                for (int kh = 0; kh < 3; kh++) {
                    float rin[2 * PX + 1];
#pragma unroll
                    for (int q = 0; q < 2 * PX + 1; q++)
                        rin[q] = s_in[cc][2 * ty + kh][2 * (tx * PX) + q];
#pragma unroll
                    for (int co = 0; co < COT; co++) {
                        float w0 = wp[co][kh * 3 + 0];
                        float w1 = wp[co][kh * 3 + 1];
                        float w2 = wp[co][kh * 3 + 2];
#pragma unroll
                        for (int p = 0; p < PX; p++)
                            acc[co][p] += rin[2 * p] * w0 + rin[2 * p + 1] * w1 + rin[2 * p + 2] * w2;
                    }
                }
            } else if (MODE == 1) {
#pragma unroll
                for (int kh = 0; kh < 3; kh++) {
                    float rin[PX + 2];
#pragma unroll
                    for (int q = 0; q < PX + 2; q++)
                        rin[q] = s_in[cc][ty + kh][tx * PX + q];
#pragma unroll
                    for (int co = 0; co < COT; co++) {
                        float w0 = wp[co][kh * 3 + 0];
                        float w1 = wp[co][kh * 3 + 1];
                        float w2 = wp[co][kh * 3 + 2];
#pragma unroll
                        for (int p = 0; p < PX; p++)
                            acc[co][p] += rin[p] * w0 + rin[p + 1] * w1 + rin[p + 2] * w2;
                    }
                }
            } else {
                // MODE 2: output-quad. Thread covers quad-row ty, cols tx*QX..+QX-1
                float ra[QX + 1], rb[QX + 1];
#pragma unroll
                for (int c = 0; c <= QX; c++) {
                    ra[c] = s_in[cc][ty][tx * QX + c];
                    rb[c] = s_in[cc][ty + 1][tx * QX + c];
                }
#pragma unroll
                for (int co = 0; co < COT; co++) {
                    float w0 = wp[co][0], w1 = wp[co][1], w2 = wp[co][2];
                    float w3 = wp[co][3], w4 = wp[co][4], w5 = wp[co][5];
                    float w6 = wp[co][6], w7 = wp[co][7], w8 = wp[co][8];
#pragma unroll
                    for (int q = 0; q < QX; q++) {
                        // top (even) output row: kh=1 taps
                        acc[co][2 * q]          += ra[q] * w4;
                        acc[co][2 * q + 1]      += ra[q] * w3 + ra[q + 1] * w5;
                        // bottom (odd) output row: kh=0,2 taps
                        acc[co][PX + 2 * q]     += ra[q] * w1 + rb[q] * w7;
                        acc[co][PX + 2 * q + 1] += ra[q] * w0 + ra[q + 1] * w2
                                                 + rb[q] * w6 + rb[q + 1] * w8;
                    }
                }
            }
        }
    }

    // ---- store ----
    const int owb = ow0 + tx * PX;
    if (SPLIT == 1) {
#pragma unroll
        for (int co = 0; co < COT; co++) {
            int gco = cob + cg * COT + co;
            float b = __ldg(&bias[gco]);
            if (MODE == 2) {
                int ohT = oh0 + 2 * ty;
                float* opT = out + ((size_t)(n * Co + gco) * Hout + ohT) * Wout + owb;
                float* opB = opT + Wout;
#pragma unroll
                for (int p0 = 0; p0 < PX; p0 += 4) {
                    float4 vT, vB;
                    vT.x = acc[co][p0 + 0] + b; vT.y = acc[co][p0 + 1] + b;
                    vT.z = acc[co][p0 + 2] + b; vT.w = acc[co][p0 + 3] + b;
                    vB.x = acc[co][PX + p0 + 0] + b; vB.y = acc[co][PX + p0 + 1] + b;
                    vB.z = acc[co][PX + p0 + 2] + b; vB.w = acc[co][PX + p0 + 3] + b;
                    if (act) {
                        vT.x = lrelu(vT.x); vT.y = lrelu(vT.y); vT.z = lrelu(vT.z); vT.w = lrelu(vT.w);
                        vB.x = lrelu(vB.x); vB.y = lrelu(vB.y); vB.z = lrelu(vB.z); vB.w = lrelu(vB.w);
                    }
                    *(float4*)(opT + p0) = vT;
                    *(float4*)(opB + p0) = vB;
                }
            } else {
                int oh = oh0 + ty;
                float* op = out + ((size_t)(n * Co + gco) * Hout + oh) * Wout + owb;
#pragma unroll
                for (int p0 = 0; p0 < PX; p0 += 4) {
                    float4 v;
                    v.x = acc[co][p0 + 0] + b; v.y = acc[co][p0 + 1] + b;
                    v.z = acc[co][p0 + 2] + b; v.w = acc[co][p0 + 3] + b;
                    if (act) { v.x = lrelu(v.x); v.y = lrelu(v.y); v.z = lrelu(v.z); v.w = lrelu(v.w); }
                    *(float4*)(op + p0) = v;
                }
            }
        }
    } else {
        float* po = out + (size_t)blockIdx.x * ((size_t)N * Co * Hout * Wout);
#pragma unroll
        for (int co = 0; co < COT; co++) {
            int gco = cob + cg * COT + co;
            if (MODE == 2) {
                int ohT = oh0 + 2 * ty;
                float* opT = po + ((size_t)(n * Co + gco) * Hout + ohT) * Wout + owb;
                float* opB = opT + Wout;
#pragma unroll
                for (int p0 = 0; p0 < PX; p0 += 4) {
                    float4 vT, vB;
                    vT.x = acc[co][p0 + 0]; vT.y = acc[co][p0 + 1];
                    vT.z = acc[co][p0 + 2]; vT.w = acc[co][p0 + 3];
                    vB.x = acc[co][PX + p0 + 0]; vB.y = acc[co][PX + p0 + 1];
                    vB.z = acc[co][PX + p0 + 2]; vB.w = acc[co][PX + p0 + 3];
                    *(float4*)(opT + p0) = vT;
                    *(float4*)(opB + p0) = vB;
                }
            } else {
                int oh = oh0 + ty;
                float* op = po + ((size_t)(n * Co + gco) * Hout + oh) * Wout + owb;
#pragma unroll
                for (int p0 = 0; p0 < PX; p0 += 4) {
                    float4 v;
                    v.x = acc[co][p0 + 0]; v.y = acc[co][p0 + 1];
                    v.z = acc[co][p0 + 2]; v.w = acc[co][p0 + 3];
                    *(float4*)(op + p0) = v;
                }
            }
        }
    }
}

// ---------------------------------------------------------------------------
// split-K reduce: sum S partials, add bias, optional LReLU
// ---------------------------------------------------------------------------
__global__ void splitk_reduce_kernel(const float* __restrict__ part,
                                     const float* __restrict__ bias,
                                     float* __restrict__ out,
                                     int S, int per, int HW, int Co, int act)
{
    int i = blockIdx.x * blockDim.x + threadIdx.x;
    if (i >= per) return;
    float s = 0.f;
    for (int k = 0; k < S; k++) s += part[(size_t)k * per + i];
    int c = (i / HW) % Co;
    float v = s + __ldg(&bias[c]);
    if (act) v = lrelu(v);
    out[i] = v;
}

// ---------------------------------------------------------------------------
// BatchNorm (batch stats over N,H,W) + LReLU
// ---------------------------------------------------------------------------
__global__ void bn_stats_kernel(const float* __restrict__ x, int N, int C, int HW)
{
    int c = blockIdx.x;
    int tot = N * HW;
    float s = 0.f, s2 = 0.f;
    for (int i = threadIdx.x; i < tot; i += blockDim.x) {
        int nn = i / HW, r = i % HW;
        float v = x[((size_t)nn * C + c) * HW + r];
        s += v;
        s2 += v * v;
    }
    __shared__ float rs[256], rq[256];
    rs[threadIdx.x] = s;
    rq[threadIdx.x] = s2;
    __syncthreads();
    for (int off = 128; off > 0; off >>= 1) {
        if (threadIdx.x < off) {
            rs[threadIdx.x] += rs[threadIdx.x + off];
            rq[threadIdx.x] += rq[threadIdx.x + off];
        }
        __syncthreads();
    }
    if (threadIdx.x == 0) {
        float m   = rs[0] / tot;
        float var = rq[0] / tot - m * m;
        g_mean[c] = m;
        g_rstd[c] = rsqrtf(var + 1e-5f);
    }
}

__global__ void bn_apply_kernel(float* __restrict__ x,
                                const float* __restrict__ gamma,
                                const float* __restrict__ beta,
                                int C, int HW, int total)
{
    int i = blockIdx.x * blockDim.x + threadIdx.x;
    if (i >= total) return;
    int c = (i / HW) % C;
    float v = (x[i] - g_mean[c]) * g_rstd[c] * __ldg(&gamma[c]) + __ldg(&beta[c]);
    x[i] = lrelu(v);
}

// ---------------------------------------------------------------------------
// Epilogue: 1x1 conv 64 -> 3
// ---------------------------------------------------------------------------
__global__ void ep_kernel(const float* __restrict__ in, const float* __restrict__ w,
                          const float* __restrict__ b, float* __restrict__ out,
                          int HW, int total)
{
    int i = blockIdx.x * blockDim.x + threadIdx.x;
    if (i >= total) return;
    int n = i / HW;
    int r = i - n * HW;
    const float* ip = in + (size_t)n * 64 * HW + r;
    float a0 = __ldg(&b[0]), a1 = __ldg(&b[1]), a2 = __ldg(&b[2]);
#pragma unroll
    for (int c = 0; c < 64; c++) {
        float v = ip[(size_t)c * HW];
        a0 += v * __ldg(&w[c]);
        a1 += v * __ldg(&w[64 + c]);
        a2 += v * __ldg(&w[128 + c]);
    }
    out[((size_t)n * 3 + 0) * HW + r] = a0;
    out[((size_t)n * 3 + 1) * HW + r] = a1;
    out[((size_t)n * 3 + 2) * HW + r] = a2;
}

// ---------------------------------------------------------------------------
// Launch sequence
// ---------------------------------------------------------------------------
extern "C" void kernel_launch(void* const* d_in, const int* in_sizes, int n_in,
                              void* d_out, int out_size)
{
    (void)in_sizes; (void)n_in; (void)out_size;
    const float* x     = (const float*)d_in[0];
    const float* wd0   = (const float*)d_in[1];
    const float* bd0   = (const float*)d_in[2];
    const float* wd1   = (const float*)d_in[3];
    const float* bd1   = (const float*)d_in[4];
    const float* wd2   = (const float*)d_in[5];
    const float* bd2   = (const float*)d_in[6];
    const float* wd3   = (const float*)d_in[7];
    const float* bd3   = (const float*)d_in[8];
    const float* wd4   = (const float*)d_in[9];
    const float* bd4   = (const float*)d_in[10];
    const float* w_in  = (const float*)d_in[11];
    const float* b_in  = (const float*)d_in[12];
    const float* gamma = (const float*)d_in[13];
    const float* beta  = (const float*)d_in[14];
    const float* wu0   = (const float*)d_in[15];
    const float* bu0   = (const float*)d_in[16];
    const float* wu1   = (const float*)d_in[17];
    const float* bu1   = (const float*)d_in[18];
    const float* wu2   = (const float*)d_in[19];
    const float* bu2   = (const float*)d_in[20];
    const float* wu3   = (const float*)d_in[21];
    const float* bu3   = (const float*)d_in[22];
    const float* wu4   = (const float*)d_in[23];
    const float* bu4   = (const float*)d_in[24];
    const float* wep   = (const float*)d_in[25];
    const float* bep   = (const float*)d_in[26];
    float* outp = (float*)d_out;

    float *A, *B, *P;
    cudaGetSymbolAddress((void**)&A, g_bufA);
    cudaGetSymbolAddress((void**)&B, g_bufB);
    cudaGetSymbolAddress((void**)&P, g_bufP);

    // --------------- encoder (conv+lrelu+down2 fused via stride-2) ----------
    // d0: 3->64, out 256x256   tile 32x8, 16 co/block
    conv3<0, 8, 8, 4, 8, 2, 3, 1><<<dim3(8, 32, 8), 128>>>(x, wd0, bd0, A, 2, 3, 64, 256, 256, 1);
    // d1: 64->128, out 128x128
    conv3<0, 8, 8, 4, 8, 2, 8, 1><<<dim3(4, 16, 16), 128>>>(A, wd1, bd1, B, 2, 64, 128, 128, 128, 1);
    // d2: 128->256, out 64x64
    conv3<0, 8, 8, 4, 8, 2, 8, 1><<<dim3(2, 8, 32), 128>>>(B, wd2, bd2, A, 2, 128, 256, 64, 64, 1);
    // d3: 256->512, out 32x32  split-K=4
    conv3<0, 8, 8, 4, 8, 2, 8, 4><<<dim3(4, 4, 64), 128>>>(A, wd3, bd3, P, 2, 256, 512, 32, 32, 0);
    splitk_reduce_kernel<<<(2 * 512 * 1024 + 255) / 256, 256>>>(P, bd3, B, 4, 2 * 512 * 1024, 1024, 512, 1);
    // d4: 512->1024, out 16x16  tile 16x16, 32 co/block, split-K=8
    conv3<0, 4, 16, 4, 8, 4, 8, 8><<<dim3(8, 1, 64), 256>>>(B, wd4, bd4, P, 2, 512, 1024, 16, 16, 0);
    splitk_reduce_kernel<<<(2 * 1024 * 256 + 255) / 256, 256>>>(P, bd4, A, 8, 2 * 1024 * 256, 256, 1024, 1);

    // --------------- innermost conv + BN + lrelu ---------------------------
    conv3<1, 4, 16, 4, 8, 4, 8, 8><<<dim3(8, 1, 64), 256>>>(A, w_in, b_in, P, 2, 1024, 1024, 16, 16, 0);
    splitk_reduce_kernel<<<(2 * 1024 * 256 + 255) / 256, 256>>>(P, b_in, B, 8, 2 * 1024 * 256, 256, 1024, 0);
    bn_stats_kernel<<<1024, 256>>>(B, 2, 1024, 256);
    bn_apply_kernel<<<(2 * 1024 * 256 + 255) / 256, 256>>>(B, gamma, beta, 1024, 256, 2 * 1024 * 256);

    // --------------- decoder (up2+conv+lrelu, output-quad form) ------------
    // u0: 1024->512, out 32x32  tile 32x16, 16 co/block, split-K=4
    conv3<2, 4, 8, 8, 4, 4, 16, 4><<<dim3(4, 2, 64), 128>>>(B, wu0, bu0, P, 2, 1024, 512, 32, 32, 0);
    splitk_reduce_kernel<<<(2 * 512 * 1024 + 255) / 256, 256>>>(P, bu0, A, 4, 2 * 512 * 1024, 1024, 512, 1);
    // u1: 512->256, out 64x64  tile 64x8, split-K=2
    conv3<2, 8, 4, 8, 4, 4, 16, 2><<<dim3(2, 8, 32), 128>>>(A, wu1, bu1, P, 2, 512, 256, 64, 64, 0);
    splitk_reduce_kernel<<<(2 * 256 * 4096 + 255) / 256, 256>>>(P, bu1, B, 2, 2 * 256 * 4096, 4096, 256, 1);
    // u2: 256->128, out 128x128
    conv3<2, 8, 4, 8, 4, 4, 16, 1><<<dim3(2, 16, 16), 128>>>(B, wu2, bu2, A, 2, 256, 128, 128, 128, 1);
    // u3: 128->64, out 256x256
    conv3<2, 8, 4, 8, 4, 4, 16, 1><<<dim3(4, 32, 8), 128>>>(A, wu3, bu3, B, 2, 128, 64, 256, 256, 1);
    // u4: 64->64, out 512x512
    conv3<2, 8, 4, 8, 4, 4, 16, 1><<<dim3(8, 64, 8), 128>>>(B, wu4, bu4, A, 2, 64, 64, 512, 512, 1);

    // --------------- epilogue 1x1 ------------------------------------------
    ep_kernel<<<(2 * 512 * 512 + 255) / 256, 256>>>(A, wep, bep, outp, 512 * 512, 2 * 512 * 512);
}

// round 4
// speedup vs baseline: 1.3456x; 1.0989x over previous
#include <cuda_runtime.h>
#include <cstdint>

// ---------------------------------------------------------------------------
// Scratch (static __device__ globals; no allocation allowed)
// ---------------------------------------------------------------------------
__device__ float    g_bufA[33554432];   // ping  (NHWC activations)
__device__ float    g_bufB[33554432];   // pong
__device__ float    g_bufP[16777216];   // split-K partials
__device__ float    g_bufX[4194304];    // input transposed NHWC, C padded to 8
__device__ uint32_t g_whi[22012416];    // repacked weights, tf32 hi
__device__ uint32_t g_wlo[22012416];    // repacked weights, tf32 lo
__device__ float    g_mean[1024];
__device__ float    g_rstd[1024];

// decoder parity-class tap tables (mode 2, PW = 9)
__constant__ int c_tcnt[4]    = {1, 2, 2, 4};
__constant__ int c_twid[4][4] = {{4,0,0,0},{3,5,0,0},{1,7,0,0},{0,2,6,8}};
__constant__ int c_toff[4][4] = {{0,0,0,0},{0,1,0,0},{0,9,0,0},{0,1,9,10}};

__device__ __forceinline__ float lrelu(float v) { return v >= 0.f ? v : 0.01f * v; }

__device__ __forceinline__ uint32_t f2tf(float v) {
    uint32_t r;
    asm("cvt.rna.tf32.f32 %0, %1;" : "=r"(r) : "f"(v));
    return r;
}

#define MMA_TF32(ACC, A0, A1, A2, A3, B0, B1)                                   \
    asm volatile("mma.sync.aligned.m16n8k8.row.col.f32.tf32.tf32.f32 "          \
                 "{%0,%1,%2,%3}, {%4,%5,%6,%7}, {%8,%9}, {%0,%1,%2,%3};"        \
                 : "+f"(ACC[0]), "+f"(ACC[1]), "+f"(ACC[2]), "+f"(ACC[3])       \
                 : "r"(A0), "r"(A1), "r"(A2), "r"(A3), "r"(B0), "r"(B1))

// ---------------------------------------------------------------------------
// Tensor-core implicit-GEMM conv (NHWC), 3xTF32 for fp32-grade accuracy.
// MODE 0: SAME conv + stride-2 subsample   (out tile 8x8 px, patch 17x17)
// MODE 1: SAME conv stride 1               (out tile 8x8 px, patch 10x10)
// MODE 2: zero-insert up2 + SAME conv, one parity class per block
//         (out tile 8x8 quads = 16x16 px, patch 9x9)
// Block: 256 thr = 8 warps (4 M-warps x 2 N-warps). Block tile M=64 px, N=64 co.
// grid.x = SX*SPLIT, grid.y = SY, grid.z = [cls]*N*(Co/64)
// ---------------------------------------------------------------------------
template <int MODE, int SPLIT>
__global__ void __launch_bounds__(256) conv_tc(
    const float* __restrict__ in, const uint32_t* __restrict__ whi,
    const uint32_t* __restrict__ wlo, const float* __restrict__ bias,
    float* __restrict__ out, int NB, int Ci, int Co, int Hout, int Wout, int act)
{
    constexpr int PW   = (MODE == 0) ? 17 : ((MODE == 1) ? 10 : 9);
    constexpr int PH   = PW;
    constexpr int CSTR = (MODE == 0) ? 9 : 12;
    constexpr int MAXT = (MODE == 2) ? 4 : 9;

    __shared__ __align__(16) float s_p[PH * PW * CSTR];
    __shared__ uint32_t s_wh[MAXT * 512];
    __shared__ uint32_t s_wl[MAXT * 512];

    const int tid  = threadIdx.x;
    const int lane = tid & 31, w = tid >> 5;
    const int g    = lane >> 2, tig = lane & 3;
    const int wm   = w & 3, wn = w >> 2;

    const int SX    = (MODE == 2) ? (Wout >> 4) : (Wout >> 3);
    const int sx    = blockIdx.x % SX;
    const int split = blockIdx.x / SX;
    const int sy    = blockIdx.y;
    const int gpc   = Co >> 6;
    int z = blockIdx.z;
    int cls = 0;
    if (MODE == 2) { cls = z / (NB * gpc); z -= cls * (NB * gpc); }
    const int n   = z / gpc;
    const int cob = (z - n * gpc) << 6;

    const int T = (MODE == 2) ? c_tcnt[cls] : 9;

    int Hin, Win, iy0, ix0;
    if (MODE == 0)      { Hin = Hout * 2; Win = Wout * 2; iy0 = sy * 16 - 1; ix0 = sx * 16 - 1; }
    else if (MODE == 1) { Hin = Hout;     Win = Wout;     iy0 = sy * 8 - 1;  ix0 = sx * 8 - 1; }
    else                { Hin = Hout / 2; Win = Wout / 2; iy0 = sy * 8;      ix0 = sx * 8; }

    // A-fragment pixel rows for this thread: pid0 = wm*16+g (rows 2*wm, col g),
    // pid1 = pid0+8 (row 2*wm+1). Patch-space base indices:
    int s0, s1;
    if (MODE == 0) { s0 = (4 * wm) * PW + 2 * g; s1 = s0 + 2 * PW; }
    else           { s0 = (2 * wm) * PW + g;     s1 = s0 + PW; }

    float acc[4][4];
#pragma unroll
    for (int i = 0; i < 4; i++)
#pragma unroll
        for (int j = 0; j < 4; j++) acc[i][j] = 0.f;

    const float* inN = in + (size_t)n * Hin * Win * Ci;

    int ciB = 0, nci = Ci;
    if (SPLIT > 1) { nci = Ci / SPLIT; ciB = split * nci; }

#pragma unroll 1
    for (int c8 = 0; c8 < nci; c8 += 8) {
        const int ci0 = ciB + c8;
        __syncthreads();
        // ---- stage weights (hi & lo) for this ci-chunk, all taps ----
#pragma unroll 1
        for (int j = tid; j < T * 512; j += 256) {
            int t  = j >> 9;
            int r  = j & 511;
            int k  = r >> 6;
            int cc = r & 63;
            int w9 = (MODE == 2) ? c_twid[cls][t] : t;
            int src = (w9 * Ci + ci0 + k) * Co + cob + cc;
            s_wh[j] = whi[src];
            s_wl[j] = wlo[src];
        }
        // ---- stage input patch (8 channels per pixel) ----
#pragma unroll 1
        for (int s = tid; s < PH * PW; s += 256) {
            int r = s / PW, c = s - r * PW;
            int iy = iy0 + r, ix = ix0 + c;
            float4 f0 = {0.f, 0.f, 0.f, 0.f}, f1 = {0.f, 0.f, 0.f, 0.f};
            if ((unsigned)iy < (unsigned)Hin && (unsigned)ix < (unsigned)Win) {
                const float4* p = (const float4*)(inN + ((size_t)iy * Win + ix) * Ci + ci0);
                f0 = p[0];
                f1 = p[1];
            }
            if (CSTR == 12) {
                *(float4*)&s_p[s * CSTR]     = f0;
                *(float4*)&s_p[s * CSTR + 4] = f1;
            } else {
                float* d = &s_p[s * CSTR];
                d[0] = f0.x; d[1] = f0.y; d[2] = f0.z; d[3] = f0.w;
                d[4] = f1.x; d[5] = f1.y; d[6] = f1.z; d[7] = f1.w;
            }
        }
        __syncthreads();

        // ---- MMA over taps ----
#pragma unroll
        for (int t = 0; t < MAXT; t++) {
            if (MODE == 2 && t >= T) break;
            const int toff = (MODE == 2) ? c_toff[cls][t] : ((t / 3) * PW + (t % 3));
            const float* pb0 = &s_p[(s0 + toff) * CSTR];
            const float* pb1 = &s_p[(s1 + toff) * CSTR];
            float a0 = pb0[tig],     a1 = pb1[tig];
            float a2 = pb0[tig + 4], a3 = pb1[tig + 4];
            uint32_t h0 = f2tf(a0), h1 = f2tf(a1), h2 = f2tf(a2), h3 = f2tf(a3);
            uint32_t l0 = f2tf(a0 - __uint_as_float(h0));
            uint32_t l1 = f2tf(a1 - __uint_as_float(h1));
            uint32_t l2 = f2tf(a2 - __uint_as_float(h2));
            uint32_t l3 = f2tf(a3 - __uint_as_float(h3));
            const uint32_t* wb  = &s_wh[t << 9];
            const uint32_t* wbl = &s_wl[t << 9];
#pragma unroll
            for (int sub = 0; sub < 4; sub++) {
                int cw = wn * 32 + sub * 8 + g;
                uint32_t bh0 = wb[(tig << 6) + cw],        bh1 = wb[((tig + 4) << 6) + cw];
                uint32_t bl0 = wbl[(tig << 6) + cw],       bl1 = wbl[((tig + 4) << 6) + cw];
                MMA_TF32(acc[sub], h0, h1, h2, h3, bh0, bh1);
                MMA_TF32(acc[sub], h0, h1, h2, h3, bl0, bl1);
                MMA_TF32(acc[sub], l0, l1, l2, l3, bh0, bh1);
            }
        }
    }

    // ---- epilogue ----
    int ohA, ohB, ow;
    if (MODE == 2) {
        int pr = cls >> 1, pc = cls & 1;
        ohA = (sy * 8 + 2 * wm) * 2 + pr;
        ohB = (sy * 8 + 2 * wm + 1) * 2 + pr;
        ow  = (sx * 8 + g) * 2 + pc;
    } else {
        ohA = sy * 8 + 2 * wm;
        ohB = ohA + 1;
        ow  = sx * 8 + g;
    }
    const int colb = cob + wn * 32 + 2 * tig;

    if (SPLIT == 1) {
#pragma unroll
        for (int sub = 0; sub < 4; sub++) {
            int col = colb + sub * 8;
            float b0 = __ldg(&bias[col]), b1 = __ldg(&bias[col + 1]);
            float v0 = acc[sub][0] + b0, v1 = acc[sub][1] + b1;
            float v2 = acc[sub][2] + b0, v3 = acc[sub][3] + b1;
            if (act) { v0 = lrelu(v0); v1 = lrelu(v1); v2 = lrelu(v2); v3 = lrelu(v3); }
            float2* pA = (float2*)(out + (((size_t)n * Hout + ohA) * Wout + ow) * Co + col);
            float2* pB = (float2*)(out + (((size_t)n * Hout + ohB) * Wout + ow) * Co + col);
            *pA = make_float2(v0, v1);
            *pB = make_float2(v2, v3);
        }
    } else {
        float* po = out + (size_t)split * ((size_t)NB * Hout * Wout * Co);
#pragma unroll
        for (int sub = 0; sub < 4; sub++) {
            int col = colb + sub * 8;
            float2* pA = (float2*)(po + (((size_t)n * Hout + ohA) * Wout + ow) * Co + col);
            float2* pB = (float2*)(po + (((size_t)n * Hout + ohB) * Wout + ow) * Co + col);
            *pA = make_float2(acc[sub][0], acc[sub][1]);
            *pB = make_float2(acc[sub][2], acc[sub][3]);
        }
    }
}

// ---------------------------------------------------------------------------
// weight repack: w [Co][Ci][3][3] -> whi/wlo [9][Cip][Co] (tf32 hi/lo)
// ---------------------------------------------------------------------------
__global__ void repack_w(const float* __restrict__ w, uint32_t* __restrict__ whi,
                         uint32_t* __restrict__ wlo, int Ci, int Cip, int Co, int total)
{
    int j = blockIdx.x * 256 + threadIdx.x;
    if (j >= total) return;
    int t  = j / (Cip * Co);
    int r  = j - t * (Cip * Co);
    int ci = r / Co;
    int co = r - ci * Co;
    float v = 0.f;
    if (ci < Ci) v = w[((size_t)co * Ci + ci) * 9 + t];
    uint32_t h = f2tf(v);
    uint32_t l = f2tf(v - __uint_as_float(h));
    whi[j] = h;
    wlo[j] = l;
}

// ---------------------------------------------------------------------------
// input transpose NCHW -> NHWC, C=3 padded to 8
// ---------------------------------------------------------------------------
__global__ void to_nhwc8(const float* __restrict__ x, float* __restrict__ X)
{
    int i = blockIdx.x * 256 + threadIdx.x;
    if (i >= 2 * 512 * 512) return;
    int n = i >> 18;
    int p = i & 262143;
    float4 a;
    a.x = x[((size_t)n * 3 + 0) * 262144 + p];
    a.y = x[((size_t)n * 3 + 1) * 262144 + p];
    a.z = x[((size_t)n * 3 + 2) * 262144 + p];
    a.w = 0.f;
    float4 zz = {0.f, 0.f, 0.f, 0.f};
    ((float4*)X)[(size_t)i * 2]     = a;
    ((float4*)X)[(size_t)i * 2 + 1] = zz;
}

// ---------------------------------------------------------------------------
// split-K reduce (NHWC): sum S partials, add bias, optional LReLU
// ---------------------------------------------------------------------------
__global__ void reduce_k(const float* __restrict__ part, const float* __restrict__ bias,
                         float* __restrict__ out, int S, int per, int Co, int act)
{
    int i = blockIdx.x * 256 + threadIdx.x;
    if (i >= per) return;
    float s = 0.f;
    for (int k = 0; k < S; k++) s += part[(size_t)k * per + i];
    int c = i % Co;
    float v = s + __ldg(&bias[c]);
    if (act) v = lrelu(v);
    out[i] = v;
}

// ---------------------------------------------------------------------------
// BatchNorm (batch stats) on NHWC [rows=N*H*W][C]
// ---------------------------------------------------------------------------
__global__ void bn_stats(const float* __restrict__ x, int rows, int C)
{
    int c = blockIdx.x * 256 + threadIdx.x;
    if (c >= C) return;
    float s = 0.f, s2 = 0.f;
    for (int r = 0; r < rows; r++) {
        float v = x[(size_t)r * C + c];
        s += v;
        s2 += v * v;
    }
    float m   = s / rows;
    float var = s2 / rows - m * m;
    g_mean[c] = m;
    g_rstd[c] = rsqrtf(var + 1e-5f);
}

__global__ void bn_apply(float* __restrict__ x, const float* __restrict__ gamma,
                         const float* __restrict__ beta, int C, int total)
{
    int i = blockIdx.x * 256 + threadIdx.x;
    if (i >= total) return;
    int c = i % C;
    float v = (x[i] - g_mean[c]) * g_rstd[c] * __ldg(&gamma[c]) + __ldg(&beta[c]);
    x[i] = lrelu(v);
}

// ---------------------------------------------------------------------------
// Epilogue: 1x1 conv 64->3, NHWC in -> NCHW out
// ---------------------------------------------------------------------------
__global__ void ep_nhwc(const float* __restrict__ in, const float* __restrict__ w,
                        const float* __restrict__ b, float* __restrict__ out)
{
    int i = blockIdx.x * 256 + threadIdx.x;
    if (i >= 2 * 512 * 512) return;
    const float* ip = in + (size_t)i * 64;
    float a0 = __ldg(&b[0]), a1 = __ldg(&b[1]), a2 = __ldg(&b[2]);
#pragma unroll
    for (int c = 0; c < 64; c++) {
        float v = ip[c];
        a0 += v * __ldg(&w[c]);
        a1 += v * __ldg(&w[64 + c]);
        a2 += v * __ldg(&w[128 + c]);
    }
    int n = i >> 18;
    int p = i & 262143;
    out[((size_t)n * 3 + 0) * 262144 + p] = a0;
    out[((size_t)n * 3 + 1) * 262144 + p] = a1;
    out[((size_t)n * 3 + 2) * 262144 + p] = a2;
}

// ---------------------------------------------------------------------------
// Launch sequence
// ---------------------------------------------------------------------------
extern "C" void kernel_launch(void* const* d_in, const int* in_sizes, int n_in,
                              void* d_out, int out_size)
{
    (void)in_sizes; (void)n_in; (void)out_size;
    const float* x     = (const float*)d_in[0];
    const float* wd[5] = {(const float*)d_in[1], (const float*)d_in[3], (const float*)d_in[5],
                          (const float*)d_in[7], (const float*)d_in[9]};
    const float* bd[5] = {(const float*)d_in[2], (const float*)d_in[4], (const float*)d_in[6],
                          (const float*)d_in[8], (const float*)d_in[10]};
    const float* w_in  = (const float*)d_in[11];
    const float* b_in  = (const float*)d_in[12];
    const float* gamma = (const float*)d_in[13];
    const float* beta  = (const float*)d_in[14];
    const float* wu[5] = {(const float*)d_in[15], (const float*)d_in[17], (const float*)d_in[19],
                          (const float*)d_in[21], (const float*)d_in[23]};
    const float* bu[5] = {(const float*)d_in[16], (const float*)d_in[18], (const float*)d_in[20],
                          (const float*)d_in[22], (const float*)d_in[24]};
    const float* wep = (const float*)d_in[25];
    const float* bep = (const float*)d_in[26];
    float* outp = (float*)d_out;

    float *A, *B, *P, *X;
    uint32_t *WH, *WL;
    cudaGetSymbolAddress((void**)&A, g_bufA);
    cudaGetSymbolAddress((void**)&B, g_bufB);
    cudaGetSymbolAddress((void**)&P, g_bufP);
    cudaGetSymbolAddress((void**)&X, g_bufX);
    cudaGetSymbolAddress((void**)&WH, g_whi);
    cudaGetSymbolAddress((void**)&WL, g_wlo);

    // layer table: {Ci(real), Cip(padded), Co}
    const int Lci[11]  = {3, 64, 128, 256, 512, 1024, 1024, 512, 256, 128, 64};
    const int Lcip[11] = {8, 64, 128, 256, 512, 1024, 1024, 512, 256, 128, 64};
    const int Lco[11]  = {64, 128, 256, 512, 1024, 1024, 512, 256, 128, 64, 64};
    const float* Lw[11] = {wd[0], wd[1], wd[2], wd[3], wd[4], w_in, wu[0], wu[1], wu[2], wu[3], wu[4]};
    size_t off[12];
    off[0] = 0;
    for (int i = 0; i < 11; i++) off[i + 1] = off[i] + (size_t)9 * Lcip[i] * Lco[i];

    // ---- weight repack + input transpose ----
    for (int i = 0; i < 11; i++) {
        int tot = 9 * Lcip[i] * Lco[i];
        repack_w<<<(tot + 255) / 256, 256>>>(Lw[i], WH + off[i], WL + off[i],
                                             Lci[i], Lcip[i], Lco[i], tot);
    }
    to_nhwc8<<<(524288 + 255) / 256, 256>>>(x, X);

    // ---- encoder ----
    // d0: 8(pad3)->64, out 256x256
    conv_tc<0, 1><<<dim3(32, 32, 2), 256>>>(X, WH + off[0], WL + off[0], bd[0], A, 2, 8, 64, 256, 256, 1);
    // d1: 64->128, out 128x128
    conv_tc<0, 1><<<dim3(16, 16, 4), 256>>>(A, WH + off[1], WL + off[1], bd[1], B, 2, 64, 128, 128, 128, 1);
    // d2: 128->256, out 64x64
    conv_tc<0, 1><<<dim3(8, 8, 8), 256>>>(B, WH + off[2], WL + off[2], bd[2], A, 2, 128, 256, 64, 64, 1);
    // d3: 256->512, out 32x32, split2
    conv_tc<0, 2><<<dim3(8, 4, 16), 256>>>(A, WH + off[3], WL + off[3], bd[3], P, 2, 256, 512, 32, 32, 0);
    reduce_k<<<(1048576 + 255) / 256, 256>>>(P, bd[3], B, 2, 1048576, 512, 1);
    // d4: 512->1024, out 16x16, split4
    conv_tc<0, 4><<<dim3(8, 2, 32), 256>>>(B, WH + off[4], WL + off[4], bd[4], P, 2, 512, 1024, 16, 16, 0);
    reduce_k<<<(524288 + 255) / 256, 256>>>(P, bd[4], A, 4, 524288, 1024, 1);

    // ---- inner conv + BN + LReLU ----
    conv_tc<1, 4><<<dim3(8, 2, 32), 256>>>(A, WH + off[5], WL + off[5], b_in, P, 2, 1024, 1024, 16, 16, 0);
    reduce_k<<<(524288 + 255) / 256, 256>>>(P, b_in, B, 4, 524288, 1024, 0);
    bn_stats<<<4, 256>>>(B, 512, 1024);
    bn_apply<<<(524288 + 255) / 256, 256>>>(B, gamma, beta, 1024, 524288);

    // ---- decoder ----
    // u0: 1024->512, out 32x32, split2
    conv_tc<2, 2><<<dim3(4, 2, 64), 256>>>(B, WH + off[6], WL + off[6], bu[0], P, 2, 1024, 512, 32, 32, 0);
    reduce_k<<<(1048576 + 255) / 256, 256>>>(P, bu[0], A, 2, 1048576, 512, 1);
    // u1: 512->256, out 64x64
    conv_tc<2, 1><<<dim3(4, 4, 32), 256>>>(A, WH + off[7], WL + off[7], bu[1], B, 2, 512, 256, 64, 64, 1);
    // u2: 256->128, out 128x128
    conv_tc<2, 1><<<dim3(8, 8, 16), 256>>>(B, WH + off[8], WL + off[8], bu[2], A, 2, 256, 128, 128, 128, 1);
    // u3: 128->64, out 256x256
    conv_tc<2, 1><<<dim3(16, 16, 8), 256>>>(A, WH + off[9], WL + off[9], bu[3], B, 2, 128, 64, 256, 256, 1);
    // u4: 64->64, out 512x512
    conv_tc<2, 1><<<dim3(32, 32, 8), 256>>>(B, WH + off[10], WL + off[10], bu[4], A, 2, 64, 64, 512, 512, 1);

    // ---- epilogue 1x1 ----
    ep_nhwc<<<(524288 + 255) / 256, 256>>>(A, wep, bep, outp);
}

// round 5
// speedup vs baseline: 2.2861x; 1.6990x over previous
#include <cuda_runtime.h>
#include <cuda_fp16.h>
#include <cstdint>

// ---------------------------------------------------------------------------
// Scratch (static __device__ globals; no allocation allowed)
// ---------------------------------------------------------------------------
__device__ float    g_bufA[33554432];   // ping  (NHWC activations)
__device__ float    g_bufB[33554432];   // pong
__device__ float    g_bufP[16777216];   // split-K partials
__device__ float    g_bufX[8388608];    // input NHWC, C padded to 16
__device__ uint32_t g_wph[12000000];    // packed fp16-pair weights, hi
__device__ uint32_t g_wpl[12000000];    // packed fp16-pair weights, lo (residual)
__device__ float    g_mean[1024];
__device__ float    g_rstd[1024];

// decoder parity-class tap tables (mode 2, PW = 9)
__constant__ int c_tcnt[4]    = {1, 2, 2, 4};
__constant__ int c_twid[4][4] = {{4,0,0,0},{3,5,0,0},{1,7,0,0},{0,2,6,8}};
__constant__ int c_toff[4][4] = {{0,0,0,0},{0,1,0,0},{0,9,0,0},{0,1,9,10}};

__device__ __forceinline__ float lrelu(float v) { return v >= 0.f ? v : 0.01f * v; }

__device__ __forceinline__ void ldsm4(uint32_t& r0, uint32_t& r1, uint32_t& r2,
                                      uint32_t& r3, uint32_t addr)
{
    asm volatile("ldmatrix.sync.aligned.m8n8.x4.shared.b16 {%0,%1,%2,%3}, [%4];"
                 : "=r"(r0), "=r"(r1), "=r"(r2), "=r"(r3) : "r"(addr));
}

__device__ __forceinline__ void mma16816(float* acc, uint32_t a0, uint32_t a1,
                                         uint32_t a2, uint32_t a3, uint32_t b0, uint32_t b1)
{
    asm volatile("mma.sync.aligned.m16n8k16.row.col.f32.f16.f16.f32 "
                 "{%0,%1,%2,%3},{%4,%5,%6,%7},{%8,%9},{%0,%1,%2,%3};"
                 : "+f"(acc[0]), "+f"(acc[1]), "+f"(acc[2]), "+f"(acc[3])
                 : "r"(a0), "r"(a1), "r"(a2), "r"(a3), "r"(b0), "r"(b1));
}

// ---------------------------------------------------------------------------
// Tensor-core implicit-GEMM conv (NHWC), fp16 3-term split (hh+hl+lh).
// MODE 0: SAME conv + stride-2 subsample   (out tile 8x8 px, patch 17x17)
// MODE 1: SAME conv stride 1               (out tile 8x8 px, patch 10x10)
// MODE 2: zero-insert up2 + SAME conv, one parity class per block
//         (out tile 8x8 quads = 16x16 px, patch 9x9)
// Block: 256 thr = 8 warps (4 M-warps x 2 N-warps). Block tile M=64 px, N=64 co.
// Channel chunk = 16 (one k16 MMA K-slice). A via ldmatrix from pre-split
// fp16 hi/lo patches; B via packed-pair LDS.
// ---------------------------------------------------------------------------
template <int MODE, int SPLIT>
__global__ void __launch_bounds__(256) conv_tc(
    const float* __restrict__ in, const uint32_t* __restrict__ wph,
    const uint32_t* __restrict__ wpl, const float* __restrict__ bias,
    float* __restrict__ out, int NB, int Ci, int Co, int Hout, int Wout, int act)
{
    constexpr int PW   = (MODE == 0) ? 17 : ((MODE == 1) ? 10 : 9);
    constexpr int PH   = PW;
    constexpr int NPX  = PH * PW;
    constexpr int CSTR = 24;                       // halves per pixel row (16 used)
    constexpr int MAXT = (MODE == 2) ? 4 : 9;

    extern __shared__ __align__(16) char smem[];
    __half*   s_hi  = (__half*)smem;
    __half*   s_lo  = s_hi + NPX * CSTR;
    uint32_t* s_wh  = (uint32_t*)(s_lo + NPX * CSTR);
    uint32_t* s_wl  = s_wh + MAXT * 512;

    const int tid  = threadIdx.x;
    const int lane = tid & 31, w = tid >> 5;
    const int g    = lane >> 2, tig = lane & 3;
    const int wm   = w & 3, wn = w >> 2;

    const int SX    = (MODE == 2) ? (Wout >> 4) : (Wout >> 3);
    const int sx    = blockIdx.x % SX;
    const int split = blockIdx.x / SX;
    const int sy    = blockIdx.y;
    const int gpc   = Co >> 6;
    int z = blockIdx.z;
    int cls = 0;
    if (MODE == 2) { cls = z / (NB * gpc); z -= cls * (NB * gpc); }
    const int n   = z / gpc;
    const int cob = (z - n * gpc) << 6;

    const int T = (MODE == 2) ? c_tcnt[cls] : 9;

    int Hin, Win, iy0, ix0;
    if (MODE == 0)      { Hin = Hout * 2; Win = Wout * 2; iy0 = sy * 16 - 1; ix0 = sx * 16 - 1; }
    else if (MODE == 1) { Hin = Hout;     Win = Wout;     iy0 = sy * 8 - 1;  ix0 = sx * 8 - 1; }
    else                { Hin = Hout / 2; Win = Wout / 2; iy0 = sy * 8;      ix0 = sx * 8; }

    // ldmatrix per-lane row address (patch-space pixel + k-half)
    const int lr   = lane & 7;
    const int sel  = lane >> 3;
    const int row8 = sel & 1;
    const int kh2  = sel >> 1;
    int pix;
    if (MODE == 0) pix = (4 * wm + 2 * row8) * PW + 2 * lr;
    else           pix = (2 * wm + row8) * PW + lr;
    const uint32_t offb    = (uint32_t)((pix * CSTR + kh2 * 8) * 2);
    const uint32_t hi_base = (uint32_t)__cvta_generic_to_shared(s_hi) + offb;
    const uint32_t lo_base = (uint32_t)__cvta_generic_to_shared(s_lo) + offb;

    float acc[4][4];
#pragma unroll
    for (int i = 0; i < 4; i++)
#pragma unroll
        for (int j = 0; j < 4; j++) acc[i][j] = 0.f;

    const float* inN = in + (size_t)n * Hin * Win * Ci;
    const int Cp = Ci >> 1;                       // packed pairs per tap row

    int ciB = 0, nci = Ci;
    if (SPLIT > 1) { nci = Ci / SPLIT; ciB = split * nci; }

#pragma unroll 1
    for (int c16 = 0; c16 < nci; c16 += 16) {
        const int ci0 = ciB + c16;
        __syncthreads();
        // ---- stage packed fp16-pair weights (hi & lo), all taps ----
#pragma unroll 1
        for (int j = tid; j < T * 512; j += 256) {
            int t  = j >> 9;
            int r  = j & 511;
            int k2 = r >> 6;
            int cc = r & 63;
            int w9 = (MODE == 2) ? c_twid[cls][t] : t;
            int src = (w9 * Cp + (ci0 >> 1) + k2) * Co + cob + cc;
            s_wh[j] = wph[src];
            s_wl[j] = wpl[src];
        }
        // ---- stage input patch: fp16 hi/lo split, 16 channels/pixel ----
#pragma unroll 1
        for (int s = tid; s < NPX; s += 256) {
            int r = s / PW, c = s - r * PW;
            int iy = iy0 + r, ix = ix0 + c;
            union { __half h[16]; uint4 u[2]; } Uh, Ul;
            if ((unsigned)iy < (unsigned)Hin && (unsigned)ix < (unsigned)Win) {
                const float4* p = (const float4*)(inN + ((size_t)iy * Win + ix) * Ci + ci0);
#pragma unroll
                for (int q = 0; q < 4; q++) {
                    float4 f = p[q];
                    float vv[4] = {f.x, f.y, f.z, f.w};
#pragma unroll
                    for (int e = 0; e < 4; e++) {
                        __half h = __float2half_rn(vv[e]);
                        Uh.h[q * 4 + e] = h;
                        Ul.h[q * 4 + e] = __float2half_rn(vv[e] - __half2float(h));
                    }
                }
            } else {
                Uh.u[0] = make_uint4(0, 0, 0, 0); Uh.u[1] = make_uint4(0, 0, 0, 0);
                Ul.u[0] = make_uint4(0, 0, 0, 0); Ul.u[1] = make_uint4(0, 0, 0, 0);
            }
            *(uint4*)&s_hi[s * CSTR]     = Uh.u[0];
            *(uint4*)&s_hi[s * CSTR + 8] = Uh.u[1];
            *(uint4*)&s_lo[s * CSTR]     = Ul.u[0];
            *(uint4*)&s_lo[s * CSTR + 8] = Ul.u[1];
        }
        __syncthreads();

        // ---- MMA over taps ----
#pragma unroll
        for (int t = 0; t < MAXT; t++) {
            if (MODE == 2 && t >= T) break;
            const int toff = (MODE == 2) ? c_toff[cls][t] : ((t / 3) * PW + (t % 3));
            const uint32_t ab = (uint32_t)(toff * CSTR * 2);
            uint32_t ah0, ah1, ah2, ah3, al0, al1, al2, al3;
            ldsm4(ah0, ah1, ah2, ah3, hi_base + ab);
            ldsm4(al0, al1, al2, al3, lo_base + ab);
            const uint32_t* wb  = &s_wh[t << 9];
            const uint32_t* wbl = &s_wl[t << 9];
#pragma unroll
            for (int sub = 0; sub < 4; sub++) {
                int cw = wn * 32 + sub * 8 + g;
                uint32_t bh0 = wb[(tig << 6) + cw],  bh1 = wb[((tig + 4) << 6) + cw];
                uint32_t bl0 = wbl[(tig << 6) + cw], bl1 = wbl[((tig + 4) << 6) + cw];
                mma16816(acc[sub], ah0, ah1, ah2, ah3, bh0, bh1);
                mma16816(acc[sub], ah0, ah1, ah2, ah3, bl0, bl1);
                mma16816(acc[sub], al0, al1, al2, al3, bh0, bh1);
            }
        }
    }

    // ---- epilogue ----
    int ohA, ohB, ow;
    if (MODE == 2) {
        int pr = cls >> 1, pc = cls & 1;
        ohA = (sy * 8 + 2 * wm) * 2 + pr;
        ohB = (sy * 8 + 2 * wm + 1) * 2 + pr;
        ow  = (sx * 8 + g) * 2 + pc;
    } else {
        ohA = sy * 8 + 2 * wm;
        ohB = ohA + 1;
        ow  = sx * 8 + g;
    }
    const int colb = cob + wn * 32 + 2 * tig;

    if (SPLIT == 1) {
#pragma unroll
        for (int sub = 0; sub < 4; sub++) {
            int col = colb + sub * 8;
            float b0 = __ldg(&bias[col]), b1 = __ldg(&bias[col + 1]);
            float v0 = acc[sub][0] + b0, v1 = acc[sub][1] + b1;
            float v2 = acc[sub][2] + b0, v3 = acc[sub][3] + b1;
            if (act) { v0 = lrelu(v0); v1 = lrelu(v1); v2 = lrelu(v2); v3 = lrelu(v3); }
            float2* pA = (float2*)(out + (((size_t)n * Hout + ohA) * Wout + ow) * Co + col);
            float2* pB = (float2*)(out + (((size_t)n * Hout + ohB) * Wout + ow) * Co + col);
            *pA = make_float2(v0, v1);
            *pB = make_float2(v2, v3);
        }
    } else {
        float* po = out + (size_t)split * ((size_t)NB * Hout * Wout * Co);
#pragma unroll
        for (int sub = 0; sub < 4; sub++) {
            int col = colb + sub * 8;
            float2* pA = (float2*)(po + (((size_t)n * Hout + ohA) * Wout + ow) * Co + col);
            float2* pB = (float2*)(po + (((size_t)n * Hout + ohB) * Wout + ow) * Co + col);
            *pA = make_float2(acc[sub][0], acc[sub][1]);
            *pB = make_float2(acc[sub][2], acc[sub][3]);
        }
    }
}

// ---------------------------------------------------------------------------
// weight repack: w [Co][Ci][3][3] -> packed fp16 pairs [9][Cip/2][Co], hi & lo
// ---------------------------------------------------------------------------
__global__ void repack_w(const float* __restrict__ w, uint32_t* __restrict__ wph,
                         uint32_t* __restrict__ wpl, int Ci, int Cip, int Co, int total)
{
    int j = blockIdx.x * 256 + threadIdx.x;
    if (j >= total) return;
    int cpo = Cip >> 1;
    int t  = j / (cpo * Co);
    int r  = j - t * (cpo * Co);
    int k2 = r / Co;
    int co = r - k2 * Co;
    int c0 = 2 * k2, c1 = c0 + 1;
    float v0 = (c0 < Ci) ? w[((size_t)co * Ci + c0) * 9 + t] : 0.f;
    float v1 = (c1 < Ci) ? w[((size_t)co * Ci + c1) * 9 + t] : 0.f;
    __half h0 = __float2half_rn(v0), h1 = __float2half_rn(v1);
    __half l0 = __float2half_rn(v0 - __half2float(h0));
    __half l1 = __float2half_rn(v1 - __half2float(h1));
    wph[j] = (uint32_t)__half_as_ushort(h0) | ((uint32_t)__half_as_ushort(h1) << 16);
    wpl[j] = (uint32_t)__half_as_ushort(l0) | ((uint32_t)__half_as_ushort(l1) << 16);
}

// ---------------------------------------------------------------------------
// input transpose NCHW -> NHWC, C=3 padded to 16
// ---------------------------------------------------------------------------
__global__ void to_nhwc16(const float* __restrict__ x, float* __restrict__ X)
{
    int i = blockIdx.x * 256 + threadIdx.x;
    if (i >= 2 * 512 * 512) return;
    int n = i >> 18;
    int p = i & 262143;
    float4 a;
    a.x = x[((size_t)n * 3 + 0) * 262144 + p];
    a.y = x[((size_t)n * 3 + 1) * 262144 + p];
    a.z = x[((size_t)n * 3 + 2) * 262144 + p];
    a.w = 0.f;
    float4 zz = {0.f, 0.f, 0.f, 0.f};
    ((float4*)X)[(size_t)i * 4]     = a;
    ((float4*)X)[(size_t)i * 4 + 1] = zz;
    ((float4*)X)[(size_t)i * 4 + 2] = zz;
    ((float4*)X)[(size_t)i * 4 + 3] = zz;
}

// ---------------------------------------------------------------------------
// split-K reduce (NHWC): sum S partials, add bias, optional LReLU
// ---------------------------------------------------------------------------
__global__ void reduce_k(const float* __restrict__ part, const float* __restrict__ bias,
                         float* __restrict__ out, int S, int per, int Co, int act)
{
    int i = blockIdx.x * 256 + threadIdx.x;
    if (i >= per) return;
    float s = 0.f;
    for (int k = 0; k < S; k++) s += part[(size_t)k * per + i];
    int c = i % Co;
    float v = s + __ldg(&bias[c]);
    if (act) v = lrelu(v);
    out[i] = v;
}

// ---------------------------------------------------------------------------
// BatchNorm (batch stats) on NHWC [rows=N*H*W][C]
// ---------------------------------------------------------------------------
__global__ void bn_stats(const float* __restrict__ x, int rows, int C)
{
    int c = blockIdx.x * 256 + threadIdx.x;
    if (c >= C) return;
    float s = 0.f, s2 = 0.f;
    for (int r = 0; r < rows; r++) {
        float v = x[(size_t)r * C + c];
        s += v;
        s2 += v * v;
    }
    float m   = s / rows;
    float var = s2 / rows - m * m;
    g_mean[c] = m;
    g_rstd[c] = rsqrtf(var + 1e-5f);
}

__global__ void bn_apply(float* __restrict__ x, const float* __restrict__ gamma,
                         const float* __restrict__ beta, int C, int total)
{
    int i = blockIdx.x * 256 + threadIdx.x;
    if (i >= total) return;
    int c = i % C;
    float v = (x[i] - g_mean[c]) * g_rstd[c] * __ldg(&gamma[c]) + __ldg(&beta[c]);
    x[i] = lrelu(v);
}

// ---------------------------------------------------------------------------
// Epilogue: 1x1 conv 64->3, NHWC in -> NCHW out
// ---------------------------------------------------------------------------
__global__ void ep_nhwc(const float* __restrict__ in, const float* __restrict__ w,
                        const float* __restrict__ b, float* __restrict__ out)
{
    int i = blockIdx.x * 256 + threadIdx.x;
    if (i >= 2 * 512 * 512) return;
    const float* ip = in + (size_t)i * 64;
    float a0 = __ldg(&b[0]), a1 = __ldg(&b[1]), a2 = __ldg(&b[2]);
#pragma unroll
    for (int c = 0; c < 64; c++) {
        float v = ip[c];
        a0 += v * __ldg(&w[c]);
        a1 += v * __ldg(&w[64 + c]);
        a2 += v * __ldg(&w[128 + c]);
    }
    int n = i >> 18;
    int p = i & 262143;
    out[((size_t)n * 3 + 0) * 262144 + p] = a0;
    out[((size_t)n * 3 + 1) * 262144 + p] = a1;
    out[((size_t)n * 3 + 2) * 262144 + p] = a2;
}

// ---------------------------------------------------------------------------
// Launch sequence
// ---------------------------------------------------------------------------
static const int SM_M0 = (17 * 17 * 24 * 2) * 2 + 9 * 512 * 4 * 2;   // 64608
static const int SM_M1 = (10 * 10 * 24 * 2) * 2 + 9 * 512 * 4 * 2;   // 46464
static const int SM_M2 = (9 * 9 * 24 * 2) * 2 + 4 * 512 * 4 * 2;     // 24160

extern "C" void kernel_launch(void* const* d_in, const int* in_sizes, int n_in,
                              void* d_out, int out_size)
{
    (void)in_sizes; (void)n_in; (void)out_size;
    const float* x     = (const float*)d_in[0];
    const float* wd[5] = {(const float*)d_in[1], (const float*)d_in[3], (const float*)d_in[5],
                          (const float*)d_in[7], (const float*)d_in[9]};
    const float* bd[5] = {(const float*)d_in[2], (const float*)d_in[4], (const float*)d_in[6],
                          (const float*)d_in[8], (const float*)d_in[10]};
    const float* w_in  = (const float*)d_in[11];
    const float* b_in  = (const float*)d_in[12];
    const float* gamma = (const float*)d_in[13];
    const float* beta  = (const float*)d_in[14];
    const float* wu[5] = {(const float*)d_in[15], (const float*)d_in[17], (const float*)d_in[19],
                          (const float*)d_in[21], (const float*)d_in[23]};
    const float* bu[5] = {(const float*)d_in[16], (const float*)d_in[18], (const float*)d_in[20],
                          (const float*)d_in[22], (const float*)d_in[24]};
    const float* wep = (const float*)d_in[25];
    const float* bep = (const float*)d_in[26];
    float* outp = (float*)d_out;

    float *A, *B, *P, *X;
    uint32_t *WH, *WL;
    cudaGetSymbolAddress((void**)&A, g_bufA);
    cudaGetSymbolAddress((void**)&B, g_bufB);
    cudaGetSymbolAddress((void**)&P, g_bufP);
    cudaGetSymbolAddress((void**)&X, g_bufX);
    cudaGetSymbolAddress((void**)&WH, g_wph);
    cudaGetSymbolAddress((void**)&WL, g_wpl);

    // allow >48KB dynamic smem for encoder mode (idempotent host calls)
    cudaFuncSetAttribute(conv_tc<0, 1>, cudaFuncAttributeMaxDynamicSharedMemorySize, SM_M0);
    cudaFuncSetAttribute(conv_tc<0, 2>, cudaFuncAttributeMaxDynamicSharedMemorySize, SM_M0);
    cudaFuncSetAttribute(conv_tc<0, 4>, cudaFuncAttributeMaxDynamicSharedMemorySize, SM_M0);
    cudaFuncSetAttribute(conv_tc<1, 4>, cudaFuncAttributeMaxDynamicSharedMemorySize, SM_M1);
    cudaFuncSetAttribute(conv_tc<2, 1>, cudaFuncAttributeMaxDynamicSharedMemorySize, SM_M2);
    cudaFuncSetAttribute(conv_tc<2, 2>, cudaFuncAttributeMaxDynamicSharedMemorySize, SM_M2);

    // layer table: {Ci(real), Cip(padded), Co}
    const int Lci[11]  = {3, 64, 128, 256, 512, 1024, 1024, 512, 256, 128, 64};
    const int Lcip[11] = {16, 64, 128, 256, 512, 1024, 1024, 512, 256, 128, 64};
    const int Lco[11]  = {64, 128, 256, 512, 1024, 1024, 512, 256, 128, 64, 64};
    const float* Lw[11] = {wd[0], wd[1], wd[2], wd[3], wd[4], w_in, wu[0], wu[1], wu[2], wu[3], wu[4]};
    size_t off[12];
    off[0] = 0;
    for (int i = 0; i < 11; i++) off[i + 1] = off[i] + (size_t)9 * (Lcip[i] / 2) * Lco[i];

    // ---- weight repack + input transpose ----
    for (int i = 0; i < 11; i++) {
        int tot = 9 * (Lcip[i] / 2) * Lco[i];
        repack_w<<<(tot + 255) / 256, 256>>>(Lw[i], WH + off[i], WL + off[i],
                                             Lci[i], Lcip[i], Lco[i], tot);
    }
    to_nhwc16<<<(524288 + 255) / 256, 256>>>(x, X);

    // ---- encoder ----
    // d0: 16(pad3)->64, out 256x256
    conv_tc<0, 1><<<dim3(32, 32, 2), 256, SM_M0>>>(X, WH + off[0], WL + off[0], bd[0], A, 2, 16, 64, 256, 256, 1);
    // d1: 64->128, out 128x128
    conv_tc<0, 1><<<dim3(16, 16, 4), 256, SM_M0>>>(A, WH + off[1], WL + off[1], bd[1], B, 2, 64, 128, 128, 128, 1);
    // d2: 128->256, out 64x64
    conv_tc<0, 1><<<dim3(8, 8, 8), 256, SM_M0>>>(B, WH + off[2], WL + off[2], bd[2], A, 2, 128, 256, 64, 64, 1);
    // d3: 256->512, out 32x32, split2
    conv_tc<0, 2><<<dim3(8, 4, 16), 256, SM_M0>>>(A, WH + off[3], WL + off[3], bd[3], P, 2, 256, 512, 32, 32, 0);
    reduce_k<<<(1048576 + 255) / 256, 256>>>(P, bd[3], B, 2, 1048576, 512, 1);
    // d4: 512->1024, out 16x16, split4
    conv_tc<0, 4><<<dim3(8, 2, 32), 256, SM_M0>>>(B, WH + off[4], WL + off[4], bd[4], P, 2, 512, 1024, 16, 16, 0);
    reduce_k<<<(524288 + 255) / 256, 256>>>(P, bd[4], A, 4, 524288, 1024, 1);

    // ---- inner conv + BN + LReLU ----
    conv_tc<1, 4><<<dim3(8, 2, 32), 256, SM_M1>>>(A, WH + off[5], WL + off[5], b_in, P, 2, 1024, 1024, 16, 16, 0);
    reduce_k<<<(524288 + 255) / 256, 256>>>(P, b_in, B, 4, 524288, 1024, 0);
    bn_stats<<<4, 256>>>(B, 512, 1024);
    bn_apply<<<(524288 + 255) / 256, 256>>>(B, gamma, beta, 1024, 524288);

    // ---- decoder ----
    // u0: 1024->512, out 32x32, split2
    conv_tc<2, 2><<<dim3(4, 2, 64), 256, SM_M2>>>(B, WH + off[6], WL + off[6], bu[0], P, 2, 1024, 512, 32, 32, 0);
    reduce_k<<<(1048576 + 255) / 256, 256>>>(P, bu[0], A, 2, 1048576, 512, 1);
    // u1: 512->256, out 64x64
    conv_tc<2, 1><<<dim3(4, 4, 32), 256, SM_M2>>>(A, WH + off[7], WL + off[7], bu[1], B, 2, 512, 256, 64, 64, 1);
    // u2: 256->128, out 128x128
    conv_tc<2, 1><<<dim3(8, 8, 16), 256, SM_M2>>>(B, WH + off[8], WL + off[8], bu[2], A, 2, 256, 128, 128, 128, 1);
    // u3: 128->64, out 256x256
    conv_tc<2, 1><<<dim3(16, 16, 8), 256, SM_M2>>>(A, WH + off[9], WL + off[9], bu[3], B, 2, 128, 64, 256, 256, 1);
    // u4: 64->64, out 512x512
    conv_tc<2, 1><<<dim3(32, 32, 8), 256, SM_M2>>>(B, WH + off[10], WL + off[10], bu[4], A, 2, 64, 64, 512, 512, 1);

    // ---- epilogue 1x1 ----
    ep_nhwc<<<(524288 + 255) / 256, 256>>>(A, wep, bep, outp);
}

// round 6
// speedup vs baseline: 2.9220x; 1.2781x over previous
#include <cuda_runtime.h>
#include <cuda_fp16.h>
#include <cstdint>

// ---------------------------------------------------------------------------
// Scratch (static __device__ globals; no allocation allowed)
// ---------------------------------------------------------------------------
__device__ float    g_bufA[33554432];   // ping: fp16 hi/lo planes (as halves)
__device__ float    g_bufB[33554432];   // pong
__device__ float    g_bufP[16777216];   // split-K fp32 partials
__device__ float    g_bufC[1048576];    // fp32 inner activations (BN input)
__device__ float    g_bufX[8388608];    // input hi/lo planes, C padded to 16
__device__ uint4    g_w4[5504256];      // fused B-fragment weights (hi,hi,lo,lo)
__device__ float    g_mean[1024];
__device__ float    g_rstd[1024];

// decoder parity-class tap tables (mode 2, PW = 9)
__constant__ int c_tcnt[4]    = {1, 2, 2, 4};
__constant__ int c_twid[4][4] = {{4,0,0,0},{3,5,0,0},{1,7,0,0},{0,2,6,8}};
__constant__ int c_toff[4][4] = {{0,0,0,0},{0,1,0,0},{0,9,0,0},{0,1,9,10}};

__device__ __forceinline__ float lrelu(float v) { return v >= 0.f ? v : 0.01f * v; }

__device__ __forceinline__ void cp16(uint32_t dst, const void* src, int sz)
{
    asm volatile("cp.async.cg.shared.global [%0], [%1], 16, %2;"
                 :: "r"(dst), "l"(src), "r"(sz));
}
__device__ __forceinline__ void cp_wait()
{
    asm volatile("cp.async.commit_group;");
    asm volatile("cp.async.wait_group 0;");
}

__device__ __forceinline__ void ldsm4(uint32_t& r0, uint32_t& r1, uint32_t& r2,
                                      uint32_t& r3, uint32_t addr)
{
    asm volatile("ldmatrix.sync.aligned.m8n8.x4.shared.b16 {%0,%1,%2,%3}, [%4];"
                 : "=r"(r0), "=r"(r1), "=r"(r2), "=r"(r3) : "r"(addr));
}

__device__ __forceinline__ void mma16816(float* acc, uint32_t a0, uint32_t a1,
                                         uint32_t a2, uint32_t a3, uint32_t b0, uint32_t b1)
{
    asm volatile("mma.sync.aligned.m16n8k16.row.col.f32.f16.f16.f32 "
                 "{%0,%1,%2,%3},{%4,%5,%6,%7},{%8,%9},{%0,%1,%2,%3};"
                 : "+f"(acc[0]), "+f"(acc[1]), "+f"(acc[2]), "+f"(acc[3])
                 : "r"(a0), "r"(a1), "r"(a2), "r"(a3), "r"(b0), "r"(b1));
}

__device__ __forceinline__ void split16(float v, __half& h, __half& l)
{
    h = __float2half_rn(v);
    l = __float2half_rn(v - __half2float(h));
}

// ---------------------------------------------------------------------------
// Tensor-core implicit-GEMM conv (NHWC fp16 hi/lo planes), 3-term fp16 split.
// MODE 0: SAME conv + stride-2 subsample   (out tile 8x8 px, patch 17x17)
// MODE 1: SAME conv stride 1               (out tile 8x8 px, patch 10x10)
// MODE 2: zero-insert up2 + SAME conv, one parity class per block
// Block: 256 thr = 8 warps (4 M x 2 N). Tile M=64 px, N=64 co. K-chunk 16.
// A via ldmatrix (hi & lo planes); B via one LDS.128 per sub per tap
// (fused fragment layout). Staging via cp.async.
// ---------------------------------------------------------------------------
template <int MODE, int SPLIT>
__global__ void __launch_bounds__(256) conv_tc(
    const __half* __restrict__ inHi, const __half* __restrict__ inLo,
    const uint4* __restrict__ w4, const float* __restrict__ bias,
    __half* __restrict__ outHi, __half* __restrict__ outLo,
    float* __restrict__ outP,
    int NB, int Ci, int Co, int Hout, int Wout, int act)
{
    constexpr int PW   = (MODE == 0) ? 17 : ((MODE == 1) ? 10 : 9);
    constexpr int PH   = PW;
    constexpr int NPX  = PH * PW;
    constexpr int CSTR = 24;                       // halves per pixel row (16 used)
    constexpr int MAXT = (MODE == 2) ? 4 : 9;

    extern __shared__ __align__(16) char smem[];
    __half* s_hi = (__half*)smem;
    __half* s_lo = s_hi + NPX * CSTR;
    uint4*  s_w4 = (uint4*)(s_lo + NPX * CSTR);

    const int tid  = threadIdx.x;
    const int lane = tid & 31, w = tid >> 5;
    const int g    = lane >> 2, tig = lane & 3;
    const int wm   = w & 3, wn = w >> 2;

    const int SX    = (MODE == 2) ? (Wout >> 4) : (Wout >> 3);
    const int sx    = blockIdx.x % SX;
    const int split = blockIdx.x / SX;
    const int sy    = blockIdx.y;
    const int gpc   = Co >> 6;
    int z = blockIdx.z;
    int cls = 0;
    if (MODE == 2) { cls = z / (NB * gpc); z -= cls * (NB * gpc); }
    const int n   = z / gpc;
    const int cob = (z - n * gpc) << 6;

    const int T = (MODE == 2) ? c_tcnt[cls] : 9;

    int Hin, Win, iy0, ix0;
    if (MODE == 0)      { Hin = Hout * 2; Win = Wout * 2; iy0 = sy * 16 - 1; ix0 = sx * 16 - 1; }
    else if (MODE == 1) { Hin = Hout;     Win = Wout;     iy0 = sy * 8 - 1;  ix0 = sx * 8 - 1; }
    else                { Hin = Hout / 2; Win = Wout / 2; iy0 = sy * 8;      ix0 = sx * 8; }

    // ldmatrix per-lane row address (patch-space pixel + k-half)
    const int lr   = lane & 7;
    const int sel  = lane >> 3;
    const int row8 = sel & 1;
    const int kh2  = sel >> 1;
    int pix;
    if (MODE == 0) pix = (4 * wm + 2 * row8) * PW + 2 * lr;
    else           pix = (2 * wm + row8) * PW + lr;
    const uint32_t s_hi_a = (uint32_t)__cvta_generic_to_shared(s_hi);
    const uint32_t s_lo_a = (uint32_t)__cvta_generic_to_shared(s_lo);
    const uint32_t s_w4_a = (uint32_t)__cvta_generic_to_shared(s_w4);
    const uint32_t offb   = (uint32_t)((pix * CSTR + kh2 * 8) * 2);

    float acc[4][4];
#pragma unroll
    for (int i = 0; i < 4; i++)
#pragma unroll
        for (int j = 0; j < 4; j++) acc[i][j] = 0.f;

    const int nch = Ci >> 4;
    const __half* inHiN = inHi + (size_t)n * Hin * Win * Ci;
    const __half* inLoN = inLo + (size_t)n * Hin * Win * Ci;

    int ciB = 0, nci = Ci;
    if (SPLIT > 1) { nci = Ci / SPLIT; ciB = split * nci; }

#pragma unroll 1
    for (int c16 = 0; c16 < nci; c16 += 16) {
        const int ci0 = ciB + c16;
        const int ch  = ci0 >> 4;
        __syncthreads();
        // ---- stage fused weights via cp.async ----
#pragma unroll 1
        for (int j = tid; j < T * 256; j += 256) {
            int t  = j >> 8;
            int r  = j & 255;
            int w9 = (MODE == 2) ? c_twid[cls][t] : t;
            const uint4* src = &w4[((size_t)(w9 * nch + ch) * 4 + (r >> 6)) * Co + cob + (r & 63)];
            cp16(s_w4_a + j * 16, src, 16);
        }
        // ---- stage input patch via cp.async (pure copy, zfill halo) ----
#pragma unroll 1
        for (int s = tid; s < NPX; s += 256) {
            int r = s / PW, c = s - r * PW;
            int iy = iy0 + r, ix = ix0 + c;
            bool ok = ((unsigned)iy < (unsigned)Hin) && ((unsigned)ix < (unsigned)Win);
            size_t gix = ((size_t)iy * Win + ix) * Ci + ci0;
            const __half* ph = ok ? (inHiN + gix) : inHiN;
            const __half* pl = ok ? (inLoN + gix) : inLoN;
            int sz = ok ? 16 : 0;
            uint32_t dh = s_hi_a + s * (CSTR * 2);
            uint32_t dl = s_lo_a + s * (CSTR * 2);
            cp16(dh, ph, sz);      cp16(dh + 16, ph + 8, sz);
            cp16(dl, pl, sz);      cp16(dl + 16, pl + 8, sz);
        }
        cp_wait();
        __syncthreads();

        // ---- MMA over taps ----
#pragma unroll
        for (int t = 0; t < MAXT; t++) {
            if (MODE == 2 && t >= T) break;
            const int toff = (MODE == 2) ? c_toff[cls][t] : ((t / 3) * PW + (t % 3));
            const uint32_t ab = (uint32_t)(toff * CSTR * 2);
            uint32_t ah0, ah1, ah2, ah3, al0, al1, al2, al3;
            ldsm4(ah0, ah1, ah2, ah3, s_hi_a + offb + ab);
            ldsm4(al0, al1, al2, al3, s_lo_a + offb + ab);
            const uint4* wrow = s_w4 + (t << 8) + (tig << 6);
#pragma unroll
            for (int sub = 0; sub < 4; sub++) {
                int cw = wn * 32 + sub * 8 + g;
                uint4 bq = wrow[cw];
                mma16816(acc[sub], ah0, ah1, ah2, ah3, bq.x, bq.y);
                mma16816(acc[sub], ah0, ah1, ah2, ah3, bq.z, bq.w);
                mma16816(acc[sub], al0, al1, al2, al3, bq.x, bq.y);
            }
        }
    }

    // ---- epilogue ----
    int ohA, ohB, ow;
    if (MODE == 2) {
        int pr = cls >> 1, pc = cls & 1;
        ohA = (sy * 8 + 2 * wm) * 2 + pr;
        ohB = (sy * 8 + 2 * wm + 1) * 2 + pr;
        ow  = (sx * 8 + g) * 2 + pc;
    } else {
        ohA = sy * 8 + 2 * wm;
        ohB = ohA + 1;
        ow  = sx * 8 + g;
    }
    const int colb = cob + wn * 32 + 2 * tig;

    if (SPLIT == 1) {
#pragma unroll
        for (int sub = 0; sub < 4; sub++) {
            int col = colb + sub * 8;
            float b0 = __ldg(&bias[col]), b1 = __ldg(&bias[col + 1]);
            float v0 = acc[sub][0] + b0, v1 = acc[sub][1] + b1;
            float v2 = acc[sub][2] + b0, v3 = acc[sub][3] + b1;
            if (act) { v0 = lrelu(v0); v1 = lrelu(v1); v2 = lrelu(v2); v3 = lrelu(v3); }
            __half h0, h1, h2, h3, l0, l1, l2, l3;
            split16(v0, h0, l0); split16(v1, h1, l1);
            split16(v2, h2, l2); split16(v3, h3, l3);
            size_t iA = (((size_t)n * Hout + ohA) * Wout + ow) * Co + col;
            size_t iB = (((size_t)n * Hout + ohB) * Wout + ow) * Co + col;
            *(__half2*)(outHi + iA) = __halves2half2(h0, h1);
            *(__half2*)(outHi + iB) = __halves2half2(h2, h3);
            *(__half2*)(outLo + iA) = __halves2half2(l0, l1);
            *(__half2*)(outLo + iB) = __halves2half2(l2, l3);
        }
    } else {
        float* po = outP + (size_t)split * ((size_t)NB * Hout * Wout * Co);
#pragma unroll
        for (int sub = 0; sub < 4; sub++) {
            int col = colb + sub * 8;
            float2* pA = (float2*)(po + (((size_t)n * Hout + ohA) * Wout + ow) * Co + col);
            float2* pB = (float2*)(po + (((size_t)n * Hout + ohB) * Wout + ow) * Co + col);
            *pA = make_float2(acc[sub][0], acc[sub][1]);
            *pB = make_float2(acc[sub][2], acc[sub][3]);
        }
    }
}

// ---------------------------------------------------------------------------
// weight repack: w [Co][Ci][3][3] -> fused B-fragment uint4
//   g_w4[((t*nch + ch)*4 + k4)*Co + co] = (hi pair k2=k4, hi pair k2=k4+4,
//                                          lo pair k2=k4, lo pair k2=k4+4)
// ---------------------------------------------------------------------------
__global__ void repack_w4(const float* __restrict__ w, uint4* __restrict__ out,
                          int Ci, int Cip, int Co, int total)
{
    int j = blockIdx.x * 256 + threadIdx.x;
    if (j >= total) return;
    int co = j % Co;
    int r  = j / Co;
    int k4 = r & 3; r >>= 2;
    int nch = Cip >> 4;
    int ch  = r % nch;
    int t   = r / nch;
    int cbase = ch * 16 + 2 * k4;
    int cs[4] = {cbase, cbase + 1, cbase + 8, cbase + 9};
    __half h[4], l[4];
#pragma unroll
    for (int e = 0; e < 4; e++) {
        float v = (cs[e] < Ci) ? w[((size_t)co * Ci + cs[e]) * 9 + t] : 0.f;
        split16(v, h[e], l[e]);
    }
    uint4 o;
    o.x = (uint32_t)__half_as_ushort(h[0]) | ((uint32_t)__half_as_ushort(h[1]) << 16);
    o.y = (uint32_t)__half_as_ushort(h[2]) | ((uint32_t)__half_as_ushort(h[3]) << 16);
    o.z = (uint32_t)__half_as_ushort(l[0]) | ((uint32_t)__half_as_ushort(l[1]) << 16);
    o.w = (uint32_t)__half_as_ushort(l[2]) | ((uint32_t)__half_as_ushort(l[3]) << 16);
    out[j] = o;
}

// ---------------------------------------------------------------------------
// input transpose NCHW -> NHWC hi/lo planes, C=3 padded to 16
// ---------------------------------------------------------------------------
__global__ void to_planes(const float* __restrict__ x, __half* __restrict__ Xhi,
                          __half* __restrict__ Xlo)
{
    int i = blockIdx.x * 256 + threadIdx.x;
    if (i >= 2 * 512 * 512) return;
    int n = i >> 18;
    int p = i & 262143;
    union { __half h[16]; uint4 u[2]; } H, L;
#pragma unroll
    for (int e = 0; e < 16; e++) { H.h[e] = __ushort_as_half(0); L.h[e] = __ushort_as_half(0); }
#pragma unroll
    for (int c = 0; c < 3; c++) {
        float v = x[((size_t)n * 3 + c) * 262144 + p];
        split16(v, H.h[c], L.h[c]);
    }
    ((uint4*)Xhi)[(size_t)i * 2]     = H.u[0];
    ((uint4*)Xhi)[(size_t)i * 2 + 1] = H.u[1];
    ((uint4*)Xlo)[(size_t)i * 2]     = L.u[0];
    ((uint4*)Xlo)[(size_t)i * 2 + 1] = L.u[1];
}

// ---------------------------------------------------------------------------
// split-K reduces
// ---------------------------------------------------------------------------
__global__ void reduce_k_f16(const float* __restrict__ part, const float* __restrict__ bias,
                             __half* __restrict__ oh, __half* __restrict__ ol,
                             int S, int per, int Co, int act)
{
    int i = blockIdx.x * 256 + threadIdx.x;
    if (i >= per) return;
    float s = 0.f;
    for (int k = 0; k < S; k++) s += part[(size_t)k * per + i];
    float v = s + __ldg(&bias[i % Co]);
    if (act) v = lrelu(v);
    __half h, l;
    split16(v, h, l);
    oh[i] = h;
    ol[i] = l;
}

__global__ void reduce_k_f32(const float* __restrict__ part, const float* __restrict__ bias,
                             float* __restrict__ out, int S, int per, int Co)
{
    int i = blockIdx.x * 256 + threadIdx.x;
    if (i >= per) return;
    float s = 0.f;
    for (int k = 0; k < S; k++) s += part[(size_t)k * per + i];
    out[i] = s + __ldg(&bias[i % Co]);
}

// ---------------------------------------------------------------------------
// BatchNorm (batch stats) on fp32 NHWC, apply -> hi/lo planes
// ---------------------------------------------------------------------------
__global__ void bn_stats(const float* __restrict__ x, int rows, int C)
{
    int c = blockIdx.x * 256 + threadIdx.x;
    if (c >= C) return;
    float s = 0.f, s2 = 0.f;
    for (int r = 0; r < rows; r++) {
        float v = x[(size_t)r * C + c];
        s += v;
        s2 += v * v;
    }
    float m   = s / rows;
    float var = s2 / rows - m * m;
    g_mean[c] = m;
    g_rstd[c] = rsqrtf(var + 1e-5f);
}

__global__ void bn_apply_f16(const float* __restrict__ x, const float* __restrict__ gamma,
                             const float* __restrict__ beta, __half* __restrict__ oh,
                             __half* __restrict__ ol, int C, int total)
{
    int i = blockIdx.x * 256 + threadIdx.x;
    if (i >= total) return;
    int c = i % C;
    float v = (x[i] - g_mean[c]) * g_rstd[c] * __ldg(&gamma[c]) + __ldg(&beta[c]);
    v = lrelu(v);
    __half h, l;
    split16(v, h, l);
    oh[i] = h;
    ol[i] = l;
}

// ---------------------------------------------------------------------------
// Epilogue: 1x1 conv 64->3, hi/lo planes in -> NCHW fp32 out
// ---------------------------------------------------------------------------
__global__ void ep_nhwc(const __half* __restrict__ ih, const __half* __restrict__ il,
                        const float* __restrict__ w, const float* __restrict__ b,
                        float* __restrict__ out)
{
    int i = blockIdx.x * 256 + threadIdx.x;
    if (i >= 2 * 512 * 512) return;
    const __half* ph = ih + (size_t)i * 64;
    const __half* pl = il + (size_t)i * 64;
    float a0 = __ldg(&b[0]), a1 = __ldg(&b[1]), a2 = __ldg(&b[2]);
#pragma unroll
    for (int c = 0; c < 64; c++) {
        float v = __half2float(ph[c]) + __half2float(pl[c]);
        a0 += v * __ldg(&w[c]);
        a1 += v * __ldg(&w[64 + c]);
        a2 += v * __ldg(&w[128 + c]);
    }
    int n = i >> 18;
    int p = i & 262143;
    out[((size_t)n * 3 + 0) * 262144 + p] = a0;
    out[((size_t)n * 3 + 1) * 262144 + p] = a1;
    out[((size_t)n * 3 + 2) * 262144 + p] = a2;
}

// ---------------------------------------------------------------------------
// Launch sequence
// ---------------------------------------------------------------------------
static const int SM_M0 = (17 * 17 * 24 * 2) * 2 + 9 * 256 * 16;   // 64608
static const int SM_M1 = (10 * 10 * 24 * 2) * 2 + 9 * 256 * 16;   // 46464
static const int SM_M2 = (9 * 9 * 24 * 2) * 2 + 4 * 256 * 16;     // 24160

extern "C" void kernel_launch(void* const* d_in, const int* in_sizes, int n_in,
                              void* d_out, int out_size)
{
    (void)in_sizes; (void)n_in; (void)out_size;
    const float* x     = (const float*)d_in[0];
    const float* wd[5] = {(const float*)d_in[1], (const float*)d_in[3], (const float*)d_in[5],
                          (const float*)d_in[7], (const float*)d_in[9]};
    const float* bd[5] = {(const float*)d_in[2], (const float*)d_in[4], (const float*)d_in[6],
                          (const float*)d_in[8], (const float*)d_in[10]};
    const float* w_in  = (const float*)d_in[11];
    const float* b_in  = (const float*)d_in[12];
    const float* gamma = (const float*)d_in[13];
    const float* beta  = (const float*)d_in[14];
    const float* wu[5] = {(const float*)d_in[15], (const float*)d_in[17], (const float*)d_in[19],
                          (const float*)d_in[21], (const float*)d_in[23]};
    const float* bu[5] = {(const float*)d_in[16], (const float*)d_in[18], (const float*)d_in[20],
                          (const float*)d_in[22], (const float*)d_in[24]};
    const float* wep = (const float*)d_in[25];
    const float* bep = (const float*)d_in[26];
    float* outp = (float*)d_out;

    float *A, *B, *P, *C, *X;
    uint4* W4;
    cudaGetSymbolAddress((void**)&A, g_bufA);
    cudaGetSymbolAddress((void**)&B, g_bufB);
    cudaGetSymbolAddress((void**)&P, g_bufP);
    cudaGetSymbolAddress((void**)&C, g_bufC);
    cudaGetSymbolAddress((void**)&X, g_bufX);
    cudaGetSymbolAddress((void**)&W4, g_w4);

    __half* Ahi = (__half*)A;  __half* Alo = Ahi + 33554432;
    __half* Bhi = (__half*)B;  __half* Blo = Bhi + 33554432;
    __half* Xhi = (__half*)X;  __half* Xlo = Xhi + 8388608;

    cudaFuncSetAttribute(conv_tc<0, 1>, cudaFuncAttributeMaxDynamicSharedMemorySize, SM_M0);
    cudaFuncSetAttribute(conv_tc<0, 2>, cudaFuncAttributeMaxDynamicSharedMemorySize, SM_M0);
    cudaFuncSetAttribute(conv_tc<0, 4>, cudaFuncAttributeMaxDynamicSharedMemorySize, SM_M0);
    cudaFuncSetAttribute(conv_tc<1, 4>, cudaFuncAttributeMaxDynamicSharedMemorySize, SM_M1);
    cudaFuncSetAttribute(conv_tc<2, 1>, cudaFuncAttributeMaxDynamicSharedMemorySize, SM_M2);
    cudaFuncSetAttribute(conv_tc<2, 2>, cudaFuncAttributeMaxDynamicSharedMemorySize, SM_M2);

    // layer table
    const int Lci[11]  = {3, 64, 128, 256, 512, 1024, 1024, 512, 256, 128, 64};
    const int Lcip[11] = {16, 64, 128, 256, 512, 1024, 1024, 512, 256, 128, 64};
    const int Lco[11]  = {64, 128, 256, 512, 1024, 1024, 512, 256, 128, 64, 64};
    const float* Lw[11] = {wd[0], wd[1], wd[2], wd[3], wd[4], w_in, wu[0], wu[1], wu[2], wu[3], wu[4]};
    size_t off[12];
    off[0] = 0;
    for (int i = 0; i < 11; i++) off[i + 1] = off[i] + (size_t)9 * (Lcip[i] / 16) * 4 * Lco[i];

    // ---- weight repack + input planes ----
    for (int i = 0; i < 11; i++) {
        int tot = 9 * (Lcip[i] / 16) * 4 * Lco[i];
        repack_w4<<<(tot + 255) / 256, 256>>>(Lw[i], W4 + off[i], Lci[i], Lcip[i], Lco[i], tot);
    }
    to_planes<<<(524288 + 255) / 256, 256>>>(x, Xhi, Xlo);

    // ---- encoder ----
    conv_tc<0, 1><<<dim3(32, 32, 2), 256, SM_M0>>>(Xhi, Xlo, W4 + off[0], bd[0], Ahi, Alo, nullptr, 2, 16, 64, 256, 256, 1);
    conv_tc<0, 1><<<dim3(16, 16, 4), 256, SM_M0>>>(Ahi, Alo, W4 + off[1], bd[1], Bhi, Blo, nullptr, 2, 64, 128, 128, 128, 1);
    conv_tc<0, 1><<<dim3(8, 8, 8), 256, SM_M0>>>(Bhi, Blo, W4 + off[2], bd[2], Ahi, Alo, nullptr, 2, 128, 256, 64, 64, 1);
    conv_tc<0, 2><<<dim3(8, 4, 16), 256, SM_M0>>>(Ahi, Alo, W4 + off[3], nullptr, nullptr, nullptr, P, 2, 256, 512, 32, 32, 0);
    reduce_k_f16<<<(1048576 + 255) / 256, 256>>>(P, bd[3], Bhi, Blo, 2, 1048576, 512, 1);
    conv_tc<0, 4><<<dim3(8, 2, 32), 256, SM_M0>>>(Bhi, Blo, W4 + off[4], nullptr, nullptr, nullptr, P, 2, 512, 1024, 16, 16, 0);
    reduce_k_f16<<<(524288 + 255) / 256, 256>>>(P, bd[4], Ahi, Alo, 4, 524288, 1024, 1);

    // ---- inner conv + BN + LReLU ----
    conv_tc<1, 4><<<dim3(8, 2, 32), 256, SM_M1>>>(Ahi, Alo, W4 + off[5], nullptr, nullptr, nullptr, P, 2, 1024, 1024, 16, 16, 0);
    reduce_k_f32<<<(524288 + 255) / 256, 256>>>(P, b_in, C, 4, 524288, 1024);
    bn_stats<<<4, 256>>>(C, 512, 1024);
    bn_apply_f16<<<(524288 + 255) / 256, 256>>>(C, gamma, beta, Bhi, Blo, 1024, 524288);

    // ---- decoder ----
    conv_tc<2, 2><<<dim3(4, 2, 64), 256, SM_M2>>>(Bhi, Blo, W4 + off[6], nullptr, nullptr, nullptr, P, 2, 1024, 512, 32, 32, 0);
    reduce_k_f16<<<(1048576 + 255) / 256, 256>>>(P, bu[0], Ahi, Alo, 2, 1048576, 512, 1);
    conv_tc<2, 1><<<dim3(4, 4, 32), 256, SM_M2>>>(Ahi, Alo, W4 + off[7], bu[1], Bhi, Blo, nullptr, 2, 512, 256, 64, 64, 1);
    conv_tc<2, 1><<<dim3(8, 8, 16), 256, SM_M2>>>(Bhi, Blo, W4 + off[8], bu[2], Ahi, Alo, nullptr, 2, 256, 128, 128, 128, 1);
    conv_tc<2, 1><<<dim3(16, 16, 8), 256, SM_M2>>>(Ahi, Alo, W4 + off[9], bu[3], Bhi, Blo, nullptr, 2, 128, 64, 256, 256, 1);
    conv_tc<2, 1><<<dim3(32, 32, 8), 256, SM_M2>>>(Bhi, Blo, W4 + off[10], bu[4], Ahi, Alo, nullptr, 2, 64, 64, 512, 512, 1);

    // ---- epilogue 1x1 ----
    ep_nhwc<<<(524288 + 255) / 256, 256>>>(Ahi, Alo, wep, bep, outp);
}

// round 10
// speedup vs baseline: 3.7977x; 1.2997x over previous
#include <cuda_runtime.h>
#include <cuda_fp16.h>
#include <cstdint>

// ---------------------------------------------------------------------------
// Scratch (static __device__ globals; no allocation allowed)
// ---------------------------------------------------------------------------
__device__ float    g_bufA[33554432];   // ping: fp16 hi/lo planes (as halves)
__device__ float    g_bufB[33554432];   // pong
__device__ float    g_bufP[16777216];   // split-K fp32 partials
__device__ float    g_bufC[1048576];    // fp32 inner activations (BN input)
__device__ float    g_bufX[8388608];    // input hi/lo planes, C padded to 16
__device__ uint4    g_w4[5504256];      // fused B-fragment weights (hi,hi,lo,lo)
__device__ float    g_mean[1024];
__device__ float    g_rstd[1024];

// decoder parity-class tap tables (mode 2, PW = 9)
__constant__ int c_tcnt[4]    = {1, 2, 2, 4};
__constant__ int c_twid[4][4] = {{4,0,0,0},{3,5,0,0},{1,7,0,0},{0,2,6,8}};
__constant__ int c_toff[4][4] = {{0,0,0,0},{0,1,0,0},{0,9,0,0},{0,1,9,10}};

// fused-repack layer tables (element = one uint4 = 4 weights hi+lo)
__constant__ int rk_ci[11]  = {3, 64, 128, 256, 512, 1024, 1024, 512, 256, 128, 64};
__constant__ int rk_cip[11] = {16, 64, 128, 256, 512, 1024, 1024, 512, 256, 128, 64};
__constant__ int rk_co[11]  = {64, 128, 256, 512, 1024, 1024, 512, 256, 128, 64, 64};
// offsets: cumulative 9*(Cip/16)*4*Co per layer (VERIFIED against host off[])
__constant__ int rk_offs[12] = {0, 2304, 20736, 94464, 389376, 1569024, 3928320,
                                5107968, 5402880, 5476608, 5495040, 5504256};

__device__ __forceinline__ float lrelu(float v) { return v >= 0.f ? v : 0.01f * v; }

__device__ __forceinline__ void cp16(uint32_t dst, const void* src, int sz)
{
    asm volatile("cp.async.cg.shared.global [%0], [%1], 16, %2;"
                 :: "r"(dst), "l"(src), "r"(sz));
}
__device__ __forceinline__ void cp_wait()
{
    asm volatile("cp.async.commit_group;");
    asm volatile("cp.async.wait_group 0;");
}

__device__ __forceinline__ void ldsm4(uint32_t& r0, uint32_t& r1, uint32_t& r2,
                                      uint32_t& r3, uint32_t addr)
{
    asm volatile("ldmatrix.sync.aligned.m8n8.x4.shared.b16 {%0,%1,%2,%3}, [%4];"
                 : "=r"(r0), "=r"(r1), "=r"(r2), "=r"(r3) : "r"(addr));
}

__device__ __forceinline__ void mma16816(float* acc, uint32_t a0, uint32_t a1,
                                         uint32_t a2, uint32_t a3, uint32_t b0, uint32_t b1)
{
    asm volatile("mma.sync.aligned.m16n8k16.row.col.f32.f16.f16.f32 "
                 "{%0,%1,%2,%3},{%4,%5,%6,%7},{%8,%9},{%0,%1,%2,%3};"
                 : "+f"(acc[0]), "+f"(acc[1]), "+f"(acc[2]), "+f"(acc[3])
                 : "r"(a0), "r"(a1), "r"(a2), "r"(a3), "r"(b0), "r"(b1));
}

__device__ __forceinline__ void split16(float v, __half& h, __half& l)
{
    h = __float2half_rn(v);
    l = __float2half_rn(v - __half2float(h));
}

// ---------------------------------------------------------------------------
// Tensor-core implicit-GEMM conv (NHWC fp16 hi/lo planes), 3-term fp16 split.
// MF = M-fragments per warp (tile M = 64*MF pixels). N tile = 64 co.
// MODE 0: SAME conv + stride-2 subsample   (block covers 8*MF output rows)
// MODE 1: SAME conv stride 1               (block covers 8*MF output rows)
// MODE 2: zero-insert up2 + SAME conv, one parity class per block
// Block: 256 thr = 8 warps (4 M x 2 N). K-chunk 16 channels.
// ---------------------------------------------------------------------------
template <int MODE, int SPLIT, int MF>
__global__ void __launch_bounds__(256) conv_tc(
    const __half* __restrict__ inHi, const __half* __restrict__ inLo,
    const uint4* __restrict__ w4, const float* __restrict__ bias,
    __half* __restrict__ outHi, __half* __restrict__ outLo,
    float* __restrict__ outP,
    int NB, int Ci, int Co, int Hout, int Wout, int act)
{
    constexpr int PW   = (MODE == 0) ? 17 : ((MODE == 1) ? 10 : 9);
    constexpr int PH   = (MODE == 0) ? (16 * MF + 1) : ((MODE == 1) ? (8 * MF + 2) : (8 * MF + 1));
    constexpr int NPX  = PH * PW;
    constexpr int CSTR = 24;                       // halves per pixel row (16 used)
    constexpr int MAXT = (MODE == 2) ? 4 : 9;
    constexpr int MDEL = ((MODE == 0) ? 16 : 8) * PW * CSTR * 2;  // byte delta between M-fragments

    extern __shared__ __align__(16) char smem[];
    __half* s_hi = (__half*)smem;
    __half* s_lo = s_hi + NPX * CSTR;
    uint4*  s_w4 = (uint4*)(s_lo + NPX * CSTR);

    const int tid  = threadIdx.x;
    const int lane = tid & 31, w = tid >> 5;
    const int g    = lane >> 2, tig = lane & 3;
    const int wm   = w & 3, wn = w >> 2;

    const int SX    = (MODE == 2) ? (Wout >> 4) : (Wout >> 3);
    const int sx    = blockIdx.x % SX;
    const int split = blockIdx.x / SX;
    const int sy    = blockIdx.y;
    const int gpc   = Co >> 6;
    int z = blockIdx.z;
    int cls = 0;
    if (MODE == 2) { cls = z / (NB * gpc); z -= cls * (NB * gpc); }
    const int n   = z / gpc;
    const int cob = (z - n * gpc) << 6;

    const int T = (MODE == 2) ? c_tcnt[cls] : 9;

    int Hin, Win, iy0, ix0;
    if (MODE == 0)      { Hin = Hout * 2; Win = Wout * 2; iy0 = sy * 16 * MF - 1; ix0 = sx * 16 - 1; }
    else if (MODE == 1) { Hin = Hout;     Win = Wout;     iy0 = sy * 8 * MF - 1;  ix0 = sx * 8 - 1; }
    else                { Hin = Hout / 2; Win = Wout / 2; iy0 = sy * 8 * MF;      ix0 = sx * 8; }

    // ldmatrix per-lane row address (patch-space pixel + k-half), fragment 0
    const int lr   = lane & 7;
    const int sel  = lane >> 3;
    const int row8 = sel & 1;
    const int kh2  = sel >> 1;
    int pix;
    if (MODE == 0) pix = (4 * wm + 2 * row8) * PW + 2 * lr;
    else           pix = (2 * wm + row8) * PW + lr;
    const uint32_t s_hi_a = (uint32_t)__cvta_generic_to_shared(s_hi);
    const uint32_t s_lo_a = (uint32_t)__cvta_generic_to_shared(s_lo);
    const uint32_t s_w4_a = (uint32_t)__cvta_generic_to_shared(s_w4);
    const uint32_t offb   = (uint32_t)((pix * CSTR + kh2 * 8) * 2);

    float acc[MF][4][4];
#pragma unroll
    for (int m = 0; m < MF; m++)
#pragma unroll
        for (int i = 0; i < 4; i++)
#pragma unroll
            for (int j = 0; j < 4; j++) acc[m][i][j] = 0.f;

    const int nch = Ci >> 4;
    const __half* inHiN = inHi + (size_t)n * Hin * Win * Ci;
    const __half* inLoN = inLo + (size_t)n * Hin * Win * Ci;

    int ciB = 0, nci = Ci;
    if (SPLIT > 1) { nci = Ci / SPLIT; ciB = split * nci; }

#pragma unroll 1
    for (int c16 = 0; c16 < nci; c16 += 16) {
        const int ci0 = ciB + c16;
        const int ch  = ci0 >> 4;
        __syncthreads();
        // ---- stage fused weights via cp.async ----
#pragma unroll 1
        for (int j = tid; j < T * 256; j += 256) {
            int t  = j >> 8;
            int r  = j & 255;
            int w9 = (MODE == 2) ? c_twid[cls][t] : t;
            const uint4* src = &w4[((size_t)(w9 * nch + ch) * 4 + (r >> 6)) * Co + cob + (r & 63)];
            cp16(s_w4_a + j * 16, src, 16);
        }
        // ---- stage input patch via cp.async (pure copy, zfill halo) ----
#pragma unroll 1
        for (int s = tid; s < NPX; s += 256) {
            int r = s / PW, c = s - r * PW;
            int iy = iy0 + r, ix = ix0 + c;
            bool ok = ((unsigned)iy < (unsigned)Hin) && ((unsigned)ix < (unsigned)Win);
            size_t gix = ((size_t)iy * Win + ix) * Ci + ci0;
            const __half* ph = ok ? (inHiN + gix) : inHiN;
            const __half* pl = ok ? (inLoN + gix) : inLoN;
            int sz = ok ? 16 : 0;
            uint32_t dh = s_hi_a + s * (CSTR * 2);
            uint32_t dl = s_lo_a + s * (CSTR * 2);
            cp16(dh, ph, sz);      cp16(dh + 16, ph + 8, sz);
            cp16(dl, pl, sz);      cp16(dl + 16, pl + 8, sz);
        }
        cp_wait();
        __syncthreads();

        // ---- MMA over taps ----
#pragma unroll
        for (int t = 0; t < MAXT; t++) {
            if (MODE == 2 && t >= T) break;
            const int toff = (MODE == 2) ? c_toff[cls][t] : ((t / 3) * PW + (t % 3));
            const uint32_t ab = (uint32_t)(toff * CSTR * 2);
            uint32_t ah[MF][4], al[MF][4];
#pragma unroll
            for (int m = 0; m < MF; m++) {
                ldsm4(ah[m][0], ah[m][1], ah[m][2], ah[m][3], s_hi_a + offb + ab + m * MDEL);
                ldsm4(al[m][0], al[m][1], al[m][2], al[m][3], s_lo_a + offb + ab + m * MDEL);
            }
            const uint4* wrow = s_w4 + (t << 8) + (tig << 6);
#pragma unroll
            for (int sub = 0; sub < 4; sub++) {
                int cw = wn * 32 + sub * 8 + g;
                uint4 bq = wrow[cw];
#pragma unroll
                for (int m = 0; m < MF; m++) {
                    mma16816(acc[m][sub], ah[m][0], ah[m][1], ah[m][2], ah[m][3], bq.x, bq.y);
                    mma16816(acc[m][sub], ah[m][0], ah[m][1], ah[m][2], ah[m][3], bq.z, bq.w);
                    mma16816(acc[m][sub], al[m][0], al[m][1], al[m][2], al[m][3], bq.x, bq.y);
                }
            }
        }
    }

    // ---- epilogue ----
    const int colb = cob + wn * 32 + 2 * tig;
#pragma unroll
    for (int m = 0; m < MF; m++) {
        int ohA, ohB, ow;
        if (MODE == 2) {
            int pr = cls >> 1, pc = cls & 1;
            int qr = sy * 8 * MF + 2 * wm + 8 * m;
            ohA = qr * 2 + pr;
            ohB = (qr + 1) * 2 + pr;
            ow  = (sx * 8 + g) * 2 + pc;
        } else {
            // block covers 8*MF OUTPUT rows in both MODE 0 and MODE 1
            ohA = sy * 8 * MF + 2 * wm + 8 * m;
            ohB = ohA + 1;
            ow  = sx * 8 + g;
        }
        if (SPLIT == 1) {
#pragma unroll
            for (int sub = 0; sub < 4; sub++) {
                int col = colb + sub * 8;
                float b0 = __ldg(&bias[col]), b1 = __ldg(&bias[col + 1]);
                float v0 = acc[m][sub][0] + b0, v1 = acc[m][sub][1] + b1;
                float v2 = acc[m][sub][2] + b0, v3 = acc[m][sub][3] + b1;
                if (act) { v0 = lrelu(v0); v1 = lrelu(v1); v2 = lrelu(v2); v3 = lrelu(v3); }
                __half h0, h1, h2, h3, l0, l1, l2, l3;
                split16(v0, h0, l0); split16(v1, h1, l1);
                split16(v2, h2, l2); split16(v3, h3, l3);
                size_t iA = (((size_t)n * Hout + ohA) * Wout + ow) * Co + col;
                size_t iB = (((size_t)n * Hout + ohB) * Wout + ow) * Co + col;
                *(__half2*)(outHi + iA) = __halves2half2(h0, h1);
                *(__half2*)(outHi + iB) = __halves2half2(h2, h3);
                *(__half2*)(outLo + iA) = __halves2half2(l0, l1);
                *(__half2*)(outLo + iB) = __halves2half2(l2, l3);
            }
        } else {
            float* po = outP + (size_t)split * ((size_t)NB * Hout * Wout * Co);
#pragma unroll
            for (int sub = 0; sub < 4; sub++) {
                int col = colb + sub * 8;
                float2* pA = (float2*)(po + (((size_t)n * Hout + ohA) * Wout + ow) * Co + col);
                float2* pB = (float2*)(po + (((size_t)n * Hout + ohB) * Wout + ow) * Co + col);
                *pA = make_float2(acc[m][sub][0], acc[m][sub][1]);
                *pB = make_float2(acc[m][sub][2], acc[m][sub][3]);
            }
        }
    }
}

// ---------------------------------------------------------------------------
// Fused weight repack for ALL layers in ONE launch.
// w [Co][Ci][3][3] -> fused B-fragment uint4 (hi pair, hi pair, lo pair, lo pair)
// ---------------------------------------------------------------------------
struct WPtrs { const float* p[11]; };

__global__ void repack_all(WPtrs wp, uint4* __restrict__ out, int total)
{
    int j = blockIdx.x * 256 + threadIdx.x;
    if (j >= total) return;
    int L = 0;
#pragma unroll
    for (int i = 1; i < 11; i++) if (j >= rk_offs[i]) L = i;
    int jj = j - rk_offs[L];
    int Ci = rk_ci[L], Cip = rk_cip[L], Co = rk_co[L];
    const float* w = wp.p[L];

    int co = jj % Co;
    int r  = jj / Co;
    int k4 = r & 3; r >>= 2;
    int nch = Cip >> 4;
    int ch  = r % nch;
    int t   = r / nch;
    int cbase = ch * 16 + 2 * k4;
    int cs[4] = {cbase, cbase + 1, cbase + 8, cbase + 9};
    __half h[4], l[4];
#pragma unroll
    for (int e = 0; e < 4; e++) {
        float v = (cs[e] < Ci) ? w[((size_t)co * Ci + cs[e]) * 9 + t] : 0.f;
        split16(v, h[e], l[e]);
    }
    uint4 o;
    o.x = (uint32_t)__half_as_ushort(h[0]) | ((uint32_t)__half_as_ushort(h[1]) << 16);
    o.y = (uint32_t)__half_as_ushort(h[2]) | ((uint32_t)__half_as_ushort(h[3]) << 16);
    o.z = (uint32_t)__half_as_ushort(l[0]) | ((uint32_t)__half_as_ushort(l[1]) << 16);
    o.w = (uint32_t)__half_as_ushort(l[2]) | ((uint32_t)__half_as_ushort(l[3]) << 16);
    out[j] = o;
}

// ---------------------------------------------------------------------------
// input transpose NCHW -> NHWC hi/lo planes, C=3 padded to 16
// ---------------------------------------------------------------------------
__global__ void to_planes(const float* __restrict__ x, __half* __restrict__ Xhi,
                          __half* __restrict__ Xlo)
{
    int i = blockIdx.x * 256 + threadIdx.x;
    if (i >= 2 * 512 * 512) return;
    int n = i >> 18;
    int p = i & 262143;
    union { __half h[16]; uint4 u[2]; } H, L;
#pragma unroll
    for (int e = 0; e < 16; e++) { H.h[e] = __ushort_as_half(0); L.h[e] = __ushort_as_half(0); }
#pragma unroll
    for (int c = 0; c < 3; c++) {
        float v = x[((size_t)n * 3 + c) * 262144 + p];
        split16(v, H.h[c], L.h[c]);
    }
    ((uint4*)Xhi)[(size_t)i * 2]     = H.u[0];
    ((uint4*)Xhi)[(size_t)i * 2 + 1] = H.u[1];
    ((uint4*)Xlo)[(size_t)i * 2]     = L.u[0];
    ((uint4*)Xlo)[(size_t)i * 2 + 1] = L.u[1];
}

// ---------------------------------------------------------------------------
// split-K reduces
// ---------------------------------------------------------------------------
__global__ void reduce_k_f16(const float* __restrict__ part, const float* __restrict__ bias,
                             __half* __restrict__ oh, __half* __restrict__ ol,
                             int S, int per, int Co, int act)
{
    int i = blockIdx.x * 256 + threadIdx.x;
    if (i >= per) return;
    float s = 0.f;
    for (int k = 0; k < S; k++) s += part[(size_t)k * per + i];
    float v = s + __ldg(&bias[i % Co]);
    if (act) v = lrelu(v);
    __half h, l;
    split16(v, h, l);
    oh[i] = h;
    ol[i] = l;
}

__global__ void reduce_k_f32(const float* __restrict__ part, const float* __restrict__ bias,
                             float* __restrict__ out, int S, int per, int Co)
{
    int i = blockIdx.x * 256 + threadIdx.x;
    if (i >= per) return;
    float s = 0.f;
    for (int k = 0; k < S; k++) s += part[(size_t)k * per + i];
    out[i] = s + __ldg(&bias[i % Co]);
}

// ---------------------------------------------------------------------------
// BatchNorm (batch stats) on fp32 NHWC, apply -> hi/lo planes
// ---------------------------------------------------------------------------
__global__ void bn_stats(const float* __restrict__ x, int rows, int C)
{
    int c = blockIdx.x * 256 + threadIdx.x;
    if (c >= C) return;
    float s = 0.f, s2 = 0.f;
    for (int r = 0; r < rows; r++) {
        float v = x[(size_t)r * C + c];
        s += v;
        s2 += v * v;
    }
    float m   = s / rows;
    float var = s2 / rows - m * m;
    g_mean[c] = m;
    g_rstd[c] = rsqrtf(var + 1e-5f);
}

__global__ void bn_apply_f16(const float* __restrict__ x, const float* __restrict__ gamma,
                             const float* __restrict__ beta, __half* __restrict__ oh,
                             __half* __restrict__ ol, int C, int total)
{
    int i = blockIdx.x * 256 + threadIdx.x;
    if (i >= total) return;
    int c = i % C;
    float v = (x[i] - g_mean[c]) * g_rstd[c] * __ldg(&gamma[c]) + __ldg(&beta[c]);
    v = lrelu(v);
    __half h, l;
    split16(v, h, l);
    oh[i] = h;
    ol[i] = l;
}

// ---------------------------------------------------------------------------
// Epilogue: 1x1 conv 64->3, hi/lo planes in -> NCHW fp32 out
// ---------------------------------------------------------------------------
__global__ void ep_nhwc(const __half* __restrict__ ih, const __half* __restrict__ il,
                        const float* __restrict__ w, const float* __restrict__ b,
                        float* __restrict__ out)
{
    int i = blockIdx.x * 256 + threadIdx.x;
    if (i >= 2 * 512 * 512) return;
    const __half* ph = ih + (size_t)i * 64;
    const __half* pl = il + (size_t)i * 64;
    float a0 = __ldg(&b[0]), a1 = __ldg(&b[1]), a2 = __ldg(&b[2]);
#pragma unroll
    for (int c = 0; c < 64; c++) {
        float v = __half2float(ph[c]) + __half2float(pl[c]);
        a0 += v * __ldg(&w[c]);
        a1 += v * __ldg(&w[64 + c]);
        a2 += v * __ldg(&w[128 + c]);
    }
    int n = i >> 18;
    int p = i & 262143;
    out[((size_t)n * 3 + 0) * 262144 + p] = a0;
    out[((size_t)n * 3 + 1) * 262144 + p] = a1;
    out[((size_t)n * 3 + 2) * 262144 + p] = a2;
}

// ---------------------------------------------------------------------------
// Launch sequence
// ---------------------------------------------------------------------------
static const int SM_M0 = (33 * 17) * 24 * 2 * 2 + 9 * 256 * 16;   // 90720
static const int SM_M1 = (18 * 10) * 24 * 2 * 2 + 9 * 256 * 16;   // 54144
static const int SM_M2 = (17 * 9)  * 24 * 2 * 2 + 4 * 256 * 16;   // 31072

extern "C" void kernel_launch(void* const* d_in, const int* in_sizes, int n_in,
                              void* d_out, int out_size)
{
    (void)in_sizes; (void)n_in; (void)out_size;
    const float* x     = (const float*)d_in[0];
    const float* wd[5] = {(const float*)d_in[1], (const float*)d_in[3], (const float*)d_in[5],
                          (const float*)d_in[7], (const float*)d_in[9]};
    const float* bd[5] = {(const float*)d_in[2], (const float*)d_in[4], (const float*)d_in[6],
                          (const float*)d_in[8], (const float*)d_in[10]};
    const float* w_in  = (const float*)d_in[11];
    const float* b_in  = (const float*)d_in[12];
    const float* gamma = (const float*)d_in[13];
    const float* beta  = (const float*)d_in[14];
    const float* wu[5] = {(const float*)d_in[15], (const float*)d_in[17], (const float*)d_in[19],
                          (const float*)d_in[21], (const float*)d_in[23]};
    const float* bu[5] = {(const float*)d_in[16], (const float*)d_in[18], (const float*)d_in[20],
                          (const float*)d_in[22], (const float*)d_in[24]};
    const float* wep = (const float*)d_in[25];
    const float* bep = (const float*)d_in[26];
    float* outp = (float*)d_out;

    float *A, *B, *P, *C, *X;
    uint4* W4;
    cudaGetSymbolAddress((void**)&A, g_bufA);
    cudaGetSymbolAddress((void**)&B, g_bufB);
    cudaGetSymbolAddress((void**)&P, g_bufP);
    cudaGetSymbolAddress((void**)&C, g_bufC);
    cudaGetSymbolAddress((void**)&X, g_bufX);
    cudaGetSymbolAddress((void**)&W4, g_w4);

    __half* Ahi = (__half*)A;  __half* Alo = Ahi + 33554432;
    __half* Bhi = (__half*)B;  __half* Blo = Bhi + 33554432;
    __half* Xhi = (__half*)X;  __half* Xlo = Xhi + 8388608;

    cudaFuncSetAttribute(conv_tc<0, 1, 2>, cudaFuncAttributeMaxDynamicSharedMemorySize, SM_M0);
    cudaFuncSetAttribute(conv_tc<0, 2, 2>, cudaFuncAttributeMaxDynamicSharedMemorySize, SM_M0);
    cudaFuncSetAttribute(conv_tc<0, 4, 2>, cudaFuncAttributeMaxDynamicSharedMemorySize, SM_M0);
    cudaFuncSetAttribute(conv_tc<1, 4, 2>, cudaFuncAttributeMaxDynamicSharedMemorySize, SM_M1);
    cudaFuncSetAttribute(conv_tc<2, 1, 2>, cudaFuncAttributeMaxDynamicSharedMemorySize, SM_M2);
    cudaFuncSetAttribute(conv_tc<2, 4, 2>, cudaFuncAttributeMaxDynamicSharedMemorySize, SM_M2);

    // layer weight offsets (must match rk_offs): 9*(Cip/16)*4*Co
    const int Lcip[11] = {16, 64, 128, 256, 512, 1024, 1024, 512, 256, 128, 64};
    const int Lco[11]  = {64, 128, 256, 512, 1024, 1024, 512, 256, 128, 64, 64};
    size_t off[12];
    off[0] = 0;
    for (int i = 0; i < 11; i++) off[i + 1] = off[i] + (size_t)9 * (Lcip[i] / 16) * 4 * Lco[i];
    int total = (int)off[11];

    // ---- fused weight repack (one launch) + input planes ----
    WPtrs wp;
    wp.p[0] = wd[0]; wp.p[1] = wd[1]; wp.p[2] = wd[2]; wp.p[3] = wd[3]; wp.p[4] = wd[4];
    wp.p[5] = w_in;
    wp.p[6] = wu[0]; wp.p[7] = wu[1]; wp.p[8] = wu[2]; wp.p[9] = wu[3]; wp.p[10] = wu[4];
    repack_all<<<(total + 255) / 256, 256>>>(wp, W4, total);
    to_planes<<<(524288 + 255) / 256, 256>>>(x, Xhi, Xlo);

    // ---- encoder ----
    conv_tc<0, 1, 2><<<dim3(32, 16, 2), 256, SM_M0>>>(Xhi, Xlo, W4 + off[0], bd[0], Ahi, Alo, nullptr, 2, 16, 64, 256, 256, 1);
    conv_tc<0, 1, 2><<<dim3(16, 8, 4), 256, SM_M0>>>(Ahi, Alo, W4 + off[1], bd[1], Bhi, Blo, nullptr, 2, 64, 128, 128, 128, 1);
    conv_tc<0, 1, 2><<<dim3(8, 4, 8), 256, SM_M0>>>(Bhi, Blo, W4 + off[2], bd[2], Ahi, Alo, nullptr, 2, 128, 256, 64, 64, 1);
    conv_tc<0, 2, 2><<<dim3(8, 2, 16), 256, SM_M0>>>(Ahi, Alo, W4 + off[3], nullptr, nullptr, nullptr, P, 2, 256, 512, 32, 32, 0);
    reduce_k_f16<<<(1048576 + 255) / 256, 256>>>(P, bd[3], Bhi, Blo, 2, 1048576, 512, 1);
    conv_tc<0, 4, 2><<<dim3(8, 1, 32), 256, SM_M0>>>(Bhi, Blo, W4 + off[4], nullptr, nullptr, nullptr, P, 2, 512, 1024, 16, 16, 0);
    reduce_k_f16<<<(524288 + 255) / 256, 256>>>(P, bd[4], Ahi, Alo, 4, 524288, 1024, 1);

    // ---- inner conv + BN + LReLU ----
    conv_tc<1, 4, 2><<<dim3(8, 1, 32), 256, SM_M1>>>(Ahi, Alo, W4 + off[5], nullptr, nullptr, nullptr, P, 2, 1024, 1024, 16, 16, 0);
    reduce_k_f32<<<(524288 + 255) / 256, 256>>>(P, b_in, C, 4, 524288, 1024);
    bn_stats<<<4, 256>>>(C, 512, 1024);
    bn_apply_f16<<<(524288 + 255) / 256, 256>>>(C, gamma, beta, Bhi, Blo, 1024, 524288);

    // ---- decoder ----
    conv_tc<2, 4, 2><<<dim3(8, 1, 64), 256, SM_M2>>>(Bhi, Blo, W4 + off[6], nullptr, nullptr, nullptr, P, 2, 1024, 512, 32, 32, 0);
    reduce_k_f16<<<(1048576 + 255) / 256, 256>>>(P, bu[0], Ahi, Alo, 4, 1048576, 512, 1);
    conv_tc<2, 1, 2><<<dim3(4, 2, 32), 256, SM_M2>>>(Ahi, Alo, W4 + off[7], bu[1], Bhi, Blo, nullptr, 2, 512, 256, 64, 64, 1);
    conv_tc<2, 1, 2><<<dim3(8, 4, 16), 256, SM_M2>>>(Bhi, Blo, W4 + off[8], bu[2], Ahi, Alo, nullptr, 2, 256, 128, 128, 128, 1);
    conv_tc<2, 1, 2><<<dim3(16, 8, 8), 256, SM_M2>>>(Ahi, Alo, W4 + off[9], bu[3], Bhi, Blo, nullptr, 2, 128, 64, 256, 256, 1);
    conv_tc<2, 1, 2><<<dim3(32, 16, 8), 256, SM_M2>>>(Bhi, Blo, W4 + off[10], bu[4], Ahi, Alo, nullptr, 2, 64, 64, 512, 512, 1);

    // ---- epilogue 1x1 ----
    ep_nhwc<<<(524288 + 255) / 256, 256>>>(Ahi, Alo, wep, bep, outp);
}